// round 11
// baseline (speedup 1.0000x reference)
#include <cuda_runtime.h>
#include <cuda_fp16.h>
#include <math.h>
#include <stdint.h>

#define BB 128     // batch
#define DD 512     // hidden
#define GG 2048    // 4*D
#define VV 10000   // vocab
#define TT 20      // timesteps
#define NCTA 64    // persistent kernel CTAs

// ---------------- device scratch (no allocation allowed) ----------------
__device__ float g_Mtmp[GG * DD];    // W_ih0 @ W_enc (fp32, split-K red target)
__device__ float g_bias0[GG];
__device__ float g_bias0f[GG];
__device__ float g_bias1[GG];
__device__ unsigned g_bar;
// fp16 operands for GEMM1
__device__ __half g_A1f[(size_t)GG * VV];          // W_ih0 (2048,10000) fp16
__device__ __half g_B1fhi[(size_t)DD * VV];        // W_enc^T (512,10000) fp16 hi/lo
__device__ __half g_B1flo[(size_t)DD * VV];
// fp16 operand for GEMM2
__device__ __half g_B2f[(size_t)VV * DD];          // W_enc (10000,512) fp16
// fp16 recurrence state
__device__ __half g_H1f[TT * BB * DD];
__device__ __half g_h0fA[BB * DD], g_h0fB[BB * DD];
__device__ __half g_h1zf[BB * DD];
// fused, gate-interleaved cell weights (fp16 single): rows n'=d*4+gate, K=1024=[x|h]
__device__ __half g_Wc0[(size_t)GG * 1024];
__device__ __half g_Wc1[(size_t)GG * 1024];

// =========================================================================
// helpers
// =========================================================================
__device__ __forceinline__ uint32_t smem_u32(const void* p) {
    uint32_t a;
    asm("{ .reg .u64 t; cvta.to.shared.u64 t, %1; cvt.u32.u64 %0, t; }" : "=r"(a) : "l"(p));
    return a;
}
#define SWZ128(o) ((o) ^ (((o) >> 3) & 0x70))

__device__ __forceinline__ void ldsm_x4(uint32_t* r, uint32_t addr) {
    asm volatile("ldmatrix.sync.aligned.m8n8.x4.shared.b16 {%0,%1,%2,%3}, [%4];"
                 : "=r"(r[0]), "=r"(r[1]), "=r"(r[2]), "=r"(r[3]) : "r"(addr));
}
__device__ __forceinline__ void mma16816h(float* d, const uint32_t* a, const uint32_t* b) {
    asm volatile(
        "mma.sync.aligned.m16n8k16.row.col.f32.f16.f16.f32 "
        "{%0,%1,%2,%3}, {%4,%5,%6,%7}, {%8,%9}, {%0,%1,%2,%3};"
        : "+f"(d[0]), "+f"(d[1]), "+f"(d[2]), "+f"(d[3])
        : "r"(a[0]), "r"(a[1]), "r"(a[2]), "r"(a[3]), "r"(b[0]), "r"(b[1]));
}
__device__ __forceinline__ void cp_async16(uint32_t daddr, const void* g, unsigned sz) {
    asm volatile("cp.async.cg.shared.global [%0], [%1], 16, %2;"
                 :: "r"(daddr), "l"(g), "r"(sz));
}
__device__ __forceinline__ void red_addf(float* p, float v) {
    asm volatile("red.global.add.f32 [%0], %1;" :: "l"(p), "f"(v) : "memory");
}
#define CP_COMMIT() asm volatile("cp.async.commit_group;" ::: "memory")
#define CP_WAIT(n)  asm volatile("cp.async.wait_group %0;" :: "n"(n) : "memory")

// =========================================================================
// prep kernels
// =========================================================================
__global__ void prep_misc_kernel(const float* __restrict__ input_,
                                 const float* __restrict__ b_ih0, const float* __restrict__ b_hh0,
                                 const float* __restrict__ b_ih1, const float* __restrict__ b_hh1) {
    int i = blockIdx.x * blockDim.x + threadIdx.x;
    if (i == 0) g_bar = 0u;
    if (i < GG) {
        g_bias0[i] = b_ih0[i] + b_hh0[i];
        g_bias1[i] = b_ih1[i] + b_hh1[i];
    }
    if (i < BB * DD) g_h1zf[i] = __float2half_rn(0.f);
    if (i < BB * DD / 4) {
        float4 v = *(const float4*)(input_ + i * 4);
        __half h[4] = {__float2half_rn(v.x), __float2half_rn(v.y),
                       __float2half_rn(v.z), __float2half_rn(v.w)};
        *(uint2*)(g_h0fA + i * 4) = *(uint2*)h;
    }
}

__global__ void bfused_kernel(const float* __restrict__ W_ih0, const float* __restrict__ b_enc) {
    __shared__ float red[256];
    int g = blockIdx.x;
    float s = 0.f;
    for (int v = threadIdx.x; v < VV; v += 256)
        s += W_ih0[(size_t)g * VV + v] * b_enc[v];
    red[threadIdx.x] = s;
    __syncthreads();
    for (int o = 128; o > 0; o >>= 1) {
        if (threadIdx.x < o) red[threadIdx.x] += red[threadIdx.x + o];
        __syncthreads();
    }
    if (threadIdx.x == 0) g_bias0f[g] = g_bias0[g] + red[0];
}

// W_enc (10000,512) fp32 -> B1fhi/B1flo (512,10000) fp16 (fused transpose + split)
__global__ void transpose_split_f16_kernel(const float* __restrict__ src,
                                           __half* __restrict__ hi,
                                           __half* __restrict__ lo) {
    __shared__ float tile[32][33];
    int c0 = blockIdx.x * 32;
    int r0 = blockIdx.y * 32;
    int c = c0 + threadIdx.x;
    for (int i = threadIdx.y; i < 32; i += 8) {
        int r = r0 + i;
        if (r < VV) tile[i][threadIdx.x] = src[(size_t)r * DD + c];
    }
    __syncthreads();
    int r = r0 + threadIdx.x;
    if (r < VV) {
        for (int i = threadIdx.y; i < 32; i += 8) {
            float v = tile[threadIdx.x][i];
            __half h = __float2half_rn(v);
            hi[(size_t)(c0 + i) * VV + r] = h;
            lo[(size_t)(c0 + i) * VV + r] = __float2half_rn(v - __half2float(h));
        }
    }
}

// fp32 -> fp16 single
__global__ void f32_to_f16_kernel(const float* __restrict__ src, __half* __restrict__ dst, int n) {
    int i = (blockIdx.x * blockDim.x + threadIdx.x) * 4;
    if (i < n) {
        float4 v = *(const float4*)(src + i);
        __half h[4] = {__float2half_rn(v.x), __float2half_rn(v.y),
                       __float2half_rn(v.z), __float2half_rn(v.w)};
        *(uint2*)(dst + i) = *(uint2*)h;
    }
}

// fused cell weights (fp16 single): out (2048,1024): n'=d*4+gate, src n=gate*512+d,
// k<512 from srcX else srcH. grid=2048, block=256.
__global__ void build_cell_w_kernel(const float* __restrict__ srcX, const float* __restrict__ srcH,
                                    __half* __restrict__ w) {
    int idx = blockIdx.x * 256 + threadIdx.x;
    int e = idx * 4;
    int np = e >> 10, k4 = e & 1023;
    int d = np >> 2, gate = np & 3;
    int n = gate * 512 + d;
    const float* s = (k4 < 512) ? (srcX + (size_t)n * 512 + k4)
                                : (srcH + (size_t)n * 512 + (k4 - 512));
    float4 v = *(const float4*)s;
    __half h[4] = {__float2half_rn(v.x), __float2half_rn(v.y),
                   __float2half_rn(v.z), __float2half_rn(v.w)};
    *(uint2*)(w + (size_t)np * 1024 + k4) = *(uint2*)h;
}

// =========================================================================
// GEMM1 (fp16 2-term, split-K=2): Mtmp(2048,512) += A(2048,10000)f16 @ (Bhi+Blo)(512,10000)^T
// BM=256 (512 thr, 8m x 2n warps), BN=128, BK=64. grid (4, 8, 2).
// smem/buf: A 32K | Bhi 16K | Blo 16K = 64K; x2 = 128K.
// =========================================================================
#define G1_BUF 65536
#define G1_SMEM (2 * G1_BUF)
#define KSPLIT (VV / 2)   // 5000

__global__ __launch_bounds__(512) void gemm1_f16x2_kernel(
    const __half* __restrict__ A,
    const __half* __restrict__ Bhi, const __half* __restrict__ Blo,
    float* __restrict__ C)
{
    extern __shared__ char smem[];
    const uint32_t sb = smem_u32(smem);
    const int tid = threadIdx.x, wid = tid >> 5, lane = tid & 31;
    const int wm = wid & 7, wn = wid >> 3;
    const int m0 = blockIdx.y * 256, n0 = blockIdx.x * 128;
    const int kb0 = blockIdx.z * KSPLIT;
    const int kend = kb0 + KSPLIT;
    const int NT = (KSPLIT + 63) / 64;   // 79

    float acc[2][8][4];
    #pragma unroll
    for (int mt = 0; mt < 2; mt++)
        #pragma unroll
        for (int nt = 0; nt < 8; nt++)
            #pragma unroll
            for (int j = 0; j < 4; j++) acc[mt][nt][j] = 0.f;

    auto load_chunk = [&](int kt, int buf) {
        const int kc = kb0 + kt * 64;
        const uint32_t bufbase = sb + buf * G1_BUF;
        #pragma unroll
        for (int it = 0; it < 4; it++) {
            int i = it * 512 + tid;
            int r = i >> 3, c16 = i & 7;
            int gk = kc + c16 * 8;
            bool inb = gk < kend;
            cp_async16(bufbase + SWZ128(r * 128 + c16 * 16),
                       A + (inb ? ((size_t)(m0 + r) * VV + gk) : 0), inb ? 16u : 0u);
        }
        #pragma unroll
        for (int w = 0; w < 2; w++) {
            const __half* src = w ? Blo : Bhi;
            uint32_t tdst = bufbase + 32768 + w * 16384;
            #pragma unroll
            for (int it = 0; it < 2; it++) {
                int i = it * 512 + tid;
                int r = i >> 3, c16 = i & 7;
                int gk = kc + c16 * 8;
                bool inb = gk < kend;
                cp_async16(tdst + SWZ128(r * 128 + c16 * 16),
                           src + (inb ? ((size_t)(n0 + r) * VV + gk) : 0), inb ? 16u : 0u);
            }
        }
        CP_COMMIT();
    };

    load_chunk(0, 0);
    const int g8 = lane >> 3, rg = lane & 7;

    for (int kt = 0; kt < NT; kt++) {
        const int buf = kt & 1;
        if (kt + 1 < NT) { load_chunk(kt + 1, buf ^ 1); CP_WAIT(1); }
        else             { CP_WAIT(0); }
        __syncthreads();

        const uint32_t bA = sb + buf * G1_BUF;
        const uint32_t bBh = bA + 32768;
        const uint32_t bBl = bA + 49152;

        #pragma unroll
        for (int kk = 0; kk < 4; kk++) {
            const int kb = kk * 32;
            uint32_t a4[2][4], bh[8][2], bl[8][2];
            #pragma unroll
            for (int mt = 0; mt < 2; mt++) {
                int row = wm * 32 + mt * 16 + (g8 & 1) * 8 + rg;
                ldsm_x4(a4[mt], bA + SWZ128(row * 128 + kb + (g8 >> 1) * 16));
            }
            #pragma unroll
            for (int p = 0; p < 4; p++) {
                int rowb = wn * 64 + p * 16 + (g8 >> 1) * 8 + rg;
                uint32_t off = SWZ128(rowb * 128 + kb + (g8 & 1) * 16);
                uint32_t t[4];
                ldsm_x4(t, bBh + off);
                bh[2 * p][0] = t[0]; bh[2 * p][1] = t[1];
                bh[2 * p + 1][0] = t[2]; bh[2 * p + 1][1] = t[3];
                ldsm_x4(t, bBl + off);
                bl[2 * p][0] = t[0]; bl[2 * p][1] = t[1];
                bl[2 * p + 1][0] = t[2]; bl[2 * p + 1][1] = t[3];
            }
            #pragma unroll
            for (int mt = 0; mt < 2; mt++)
                #pragma unroll
                for (int nt = 0; nt < 8; nt++) {
                    mma16816h(acc[mt][nt], a4[mt], bh[nt]);
                    mma16816h(acc[mt][nt], a4[mt], bl[nt]);
                }
        }
        __syncthreads();
    }

    // split-K reduction epilogue
    #pragma unroll
    for (int mt = 0; mt < 2; mt++) {
        int row = m0 + wm * 32 + mt * 16 + (lane >> 2);
        #pragma unroll
        for (int nt = 0; nt < 8; nt++) {
            int col = n0 + wn * 64 + nt * 8 + (lane & 3) * 2;
            float* p0 = &C[(size_t)row * DD + col];
            float* p1 = &C[(size_t)(row + 8) * DD + col];
            red_addf(p0, acc[mt][nt][0]);
            red_addf(p0 + 1, acc[mt][nt][1]);
            red_addf(p1, acc[mt][nt][2]);
            red_addf(p1 + 1, acc[mt][nt][3]);
        }
    }
}

// =========================================================================
// GEMM2 (fp16 single-B): OUT(M,N) = A(M,K)f16 @ B(N,K)^T + bias.
// BM=256, BN=128, BK=64; 512 threads (8m x 2n warps).
// smem/buf: A 32K | B 16K = 48K; x2 = 96K.
// =========================================================================
#define G2_BUF 49152
#define G2_SMEM (2 * G2_BUF)

__global__ __launch_bounds__(512) void gemm2_f16_kernel(
    const __half* __restrict__ A, const __half* __restrict__ B,
    float* __restrict__ C, const float* __restrict__ bias,
    int Mtot, int Ntot, int Ktot)
{
    extern __shared__ char smem[];
    const uint32_t sb = smem_u32(smem);
    const int tid = threadIdx.x, wid = tid >> 5, lane = tid & 31;
    const int wm = wid & 7, wn = wid >> 3;
    const int m0 = blockIdx.y * 256, n0 = blockIdx.x * 128;
    const int NT = (Ktot + 63) / 64;

    float acc[2][8][4];
    #pragma unroll
    for (int mt = 0; mt < 2; mt++)
        #pragma unroll
        for (int nt = 0; nt < 8; nt++)
            #pragma unroll
            for (int j = 0; j < 4; j++) acc[mt][nt][j] = 0.f;

    auto load_chunk = [&](int kt, int buf) {
        const int kc = kt * 64;
        const uint32_t bufbase = sb + buf * G2_BUF;
        #pragma unroll
        for (int it = 0; it < 4; it++) {
            int i = it * 512 + tid;
            int r = i >> 3, c16 = i & 7;
            cp_async16(bufbase + SWZ128(r * 128 + c16 * 16),
                       A + (size_t)(m0 + r) * Ktot + kc + c16 * 8, 16);
        }
        #pragma unroll
        for (int it = 0; it < 2; it++) {
            int i = it * 512 + tid;
            int r = i >> 3, c16 = i & 7;
            int gr = n0 + r;
            bool inb = gr < Ntot;
            cp_async16(bufbase + 32768 + SWZ128(r * 128 + c16 * 16),
                       B + (inb ? ((size_t)gr * Ktot + kc + c16 * 8) : 0), inb ? 16u : 0u);
        }
        CP_COMMIT();
    };

    load_chunk(0, 0);
    const int g8 = lane >> 3, rg = lane & 7;

    for (int kt = 0; kt < NT; kt++) {
        const int buf = kt & 1;
        if (kt + 1 < NT) { load_chunk(kt + 1, buf ^ 1); CP_WAIT(1); }
        else             { CP_WAIT(0); }
        __syncthreads();

        const uint32_t bA = sb + buf * G2_BUF;
        const uint32_t bB = bA + 32768;

        #pragma unroll
        for (int kk = 0; kk < 4; kk++) {
            const int kb = kk * 32;
            uint32_t a4[2][4], b[8][2];
            #pragma unroll
            for (int mt = 0; mt < 2; mt++) {
                int row = wm * 32 + mt * 16 + (g8 & 1) * 8 + rg;
                ldsm_x4(a4[mt], bA + SWZ128(row * 128 + kb + (g8 >> 1) * 16));
            }
            #pragma unroll
            for (int p = 0; p < 4; p++) {
                int rowb = wn * 64 + p * 16 + (g8 >> 1) * 8 + rg;
                uint32_t t[4];
                ldsm_x4(t, bB + SWZ128(rowb * 128 + kb + (g8 & 1) * 16));
                b[2 * p][0] = t[0]; b[2 * p][1] = t[1];
                b[2 * p + 1][0] = t[2]; b[2 * p + 1][1] = t[3];
            }
            #pragma unroll
            for (int mt = 0; mt < 2; mt++)
                #pragma unroll
                for (int nt = 0; nt < 8; nt++)
                    mma16816h(acc[mt][nt], a4[mt], b[nt]);
        }
        __syncthreads();
    }

    #pragma unroll
    for (int mt = 0; mt < 2; mt++) {
        int row = m0 + wm * 32 + mt * 16 + (lane >> 2);
        #pragma unroll
        for (int nt = 0; nt < 8; nt++) {
            int col = n0 + wn * 64 + nt * 8 + (lane & 3) * 2;
            if (col < Ntot) {
                float b0 = bias[col], b1 = bias[col + 1];
                float2 v0 = make_float2(acc[mt][nt][0] + b0, acc[mt][nt][1] + b1);
                float2 v1 = make_float2(acc[mt][nt][2] + b0, acc[mt][nt][3] + b1);
                *(float2*)&C[(size_t)row * Ntot + col] = v0;
                *(float2*)&C[(size_t)(row + 8) * Ntot + col] = v1;
            }
        }
    }
}

// =========================================================================
// persistent LSTM recurrence, fp16 single-W, 64 CTAs x 32 gate rows.
// CTA b owns gate rows n0 = b*32 (d in [b*8, b*8+8)); 256 threads (8 warps).
// smem: W0 64K | W1 64K | A 3x16K | gates 128x33 f32 ~16.5K  = ~192.5K
// =========================================================================
#define PSM_W0 0
#define PSM_W1 65536
#define PSM_A  131072
#define PSM_G  180224
#define GSTRIDE 33
#define PERS_SMEM (180224 + 128 * GSTRIDE * 4)

__global__ __launch_bounds__(256) void lstm_persistent_kernel(
    const __half* __restrict__ Wc0, const __half* __restrict__ Wc1,
    __half* __restrict__ h0fA, __half* __restrict__ h0fB,
    const __half* __restrict__ h1zf, __half* __restrict__ H1f,
    const float* __restrict__ bias0, const float* __restrict__ bias0f,
    const float* __restrict__ bias1)
{
    extern __shared__ char smem[];
    const uint32_t sb = smem_u32(smem);
    float* gates = (float*)(smem + PSM_G);
    const int tid = threadIdx.x, wid = tid >> 5, lane = tid & 31;
    const int n0 = blockIdx.x * 32;
    const int g8 = lane >> 3, rg = lane & 7;

    // persistent weight slices: per layer 16 chunks x (32 rows x 128B) = 64KB
    #pragma unroll
    for (int L = 0; L < 2; L++) {
        const __half* src = L ? Wc1 : Wc0;
        const uint32_t dstb = L ? PSM_W1 : PSM_W0;
        #pragma unroll
        for (int it = 0; it < 16; it++) {
            int i = it * 256 + tid;
            int ch = i >> 8, r = (i >> 3) & 31, c16 = i & 7;
            cp_async16(sb + dstb + ch * 4096 + SWZ128(r * 128 + c16 * 16),
                       src + (size_t)(n0 + r) * 1024 + ch * 64 + c16 * 8, 16);
        }
    }
    CP_COMMIT();

    // hoisted bias regs: thread handles (row = idx>>3, dd = idx&7) for it in 0..3
    float rb0[4][4], rb0f[4][4], rb1[4][4];
    #pragma unroll
    for (int it = 0; it < 4; it++) {
        int idx = it * 256 + tid;
        int dd = idx & 7;
        int d = blockIdx.x * 8 + dd;
        #pragma unroll
        for (int g = 0; g < 4; g++) {
            rb0[it][g]  = bias0[g * 512 + d];
            rb0f[it][g] = bias0f[g * 512 + d];
            rb1[it][g]  = bias1[g * 512 + d];
        }
    }

    float c0r[4] = {0.f, 0.f, 0.f, 0.f}, c1r[4] = {0.f, 0.f, 0.f, 0.f};
    unsigned epoch = 0;
    int cur = 0;

    for (int t = 0; t < TT; t++) {
        #pragma unroll
        for (int layer = 0; layer < 2; layer++) {
            const __half *xf, *hf;
            int kstart;
            if (layer == 0) {
                kstart = (t == 0) ? 8 : 0;
                xf = (t == 0) ? (const __half*)0 : H1f + (size_t)(t - 1) * BB * DD;
                hf = cur ? h0fB : h0fA;
            } else {
                kstart = 0;
                xf = cur ? h0fA : h0fB;
                hf = (t == 0) ? h1zf : H1f + (size_t)(t - 1) * BB * DD;
            }
            const uint32_t wbase = sb + (layer ? PSM_W1 : PSM_W0);

            auto load_chunk = [&](int ch, int buf) {
                const __half* src = (ch < 8) ? xf : hf;
                int koff = (ch & 7) * 64;
                const uint32_t base = sb + PSM_A + buf * 16384;
                #pragma unroll
                for (int it = 0; it < 4; it++) {
                    int i = it * 256 + tid;
                    int r = i >> 3, c16 = i & 7;
                    cp_async16(base + SWZ128(r * 128 + c16 * 16),
                               src + (size_t)r * 512 + koff + c16 * 8, 16);
                }
                CP_COMMIT();
            };

            float acc[4][4];
            #pragma unroll
            for (int b = 0; b < 4; b++)
                #pragma unroll
                for (int j = 0; j < 4; j++) acc[b][j] = 0.f;

            load_chunk(kstart, 0);
            if (kstart + 1 < 16) load_chunk(kstart + 1, 1);
            for (int ch = kstart; ch < 16; ch++) {
                const int i = ch - kstart;
                if (ch + 1 < 16) { CP_WAIT(1); }
                else             { CP_WAIT(0); }
                __syncthreads();
                if (ch + 2 < 16) load_chunk(ch + 2, (i + 2) % 3);

                const uint32_t bA = sb + PSM_A + (i % 3) * 16384;
                const uint32_t bW = wbase + ch * 4096;

                #pragma unroll
                for (int kk = 0; kk < 4; kk++) {
                    const int kb = kk * 32;
                    uint32_t a4[4], t[4], t2[4];
                    int row = wid * 16 + (g8 & 1) * 8 + rg;
                    ldsm_x4(a4, bA + SWZ128(row * 128 + kb + (g8 >> 1) * 16));
                    int rowb = (g8 >> 1) * 8 + rg;
                    uint32_t offc = kb + (g8 & 1) * 16;
                    ldsm_x4(t,  bW + SWZ128(rowb * 128 + offc));
                    ldsm_x4(t2, bW + SWZ128((rowb + 16) * 128 + offc));
                    uint32_t b0[2] = {t[0], t[1]},  b1[2] = {t[2], t[3]};
                    uint32_t b2[2] = {t2[0], t2[1]}, b3[2] = {t2[2], t2[3]};
                    mma16816h(acc[0], a4, b0);
                    mma16816h(acc[1], a4, b1);
                    mma16816h(acc[2], a4, b2);
                    mma16816h(acc[3], a4, b3);
                }
            }
            __syncthreads();

            // stage gates (128 rows x 32 cols, stride 33 to dodge bank conflicts)
            {
                int r0 = wid * 16 + (lane >> 2);
                int cb = (lane & 3) * 2;
                #pragma unroll
                for (int b = 0; b < 4; b++) {
                    gates[r0 * GSTRIDE + b * 8 + cb]           = acc[b][0];
                    gates[r0 * GSTRIDE + b * 8 + cb + 1]       = acc[b][1];
                    gates[(r0 + 8) * GSTRIDE + b * 8 + cb]     = acc[b][2];
                    gates[(r0 + 8) * GSTRIDE + b * 8 + cb + 1] = acc[b][3];
                }
            }
            __syncthreads();

            __half* of = (layer == 0) ? (cur ? h0fA : h0fB) : (H1f + (size_t)t * BB * DD);
            #pragma unroll
            for (int it = 0; it < 4; it++) {
                int idx = it * 256 + tid;
                int row = idx >> 3, dd = idx & 7;
                int d = blockIdx.x * 8 + dd;
                const float* rb = (layer == 0) ? ((t == 0) ? rb0[it] : rb0f[it]) : rb1[it];
                float gi = gates[row * GSTRIDE + dd * 4 + 0] + rb[0];
                float gf = gates[row * GSTRIDE + dd * 4 + 1] + rb[1];
                float gg = gates[row * GSTRIDE + dd * 4 + 2] + rb[2];
                float go = gates[row * GSTRIDE + dd * 4 + 3] + rb[3];
                float i_ = 1.f / (1.f + expf(-gi));
                float f_ = 1.f / (1.f + expf(-gf));
                float g_ = tanhf(gg);
                float o_ = 1.f / (1.f + expf(-go));
                float* cr = (layer == 0) ? &c0r[it] : &c1r[it];
                float cn = f_ * (*cr) + i_ * g_;
                *cr = cn;
                of[row * 512 + d] = __float2half_rn(o_ * tanhf(cn));
            }

            __threadfence();
            __syncthreads();
            epoch++;
            if (tid == 0) {
                atomicAdd(&g_bar, 1u);
                unsigned target = epoch * NCTA;
                volatile unsigned* p = &g_bar;
                while (*p < target) { }
                __threadfence();
            }
            __syncthreads();
        }
        cur ^= 1;
    }
}

// =========================================================================
// host
// =========================================================================
extern "C" void kernel_launch(void* const* d_in, const int* in_sizes, int n_in,
                              void* d_out, int out_size) {
    const float* input_ = (const float*)d_in[0];
    const float* W_ih0  = (const float*)d_in[1];
    const float* W_hh0  = (const float*)d_in[2];
    const float* b_ih0  = (const float*)d_in[3];
    const float* b_hh0  = (const float*)d_in[4];
    const float* W_ih1  = (const float*)d_in[5];
    const float* W_hh1  = (const float*)d_in[6];
    const float* b_ih1  = (const float*)d_in[7];
    const float* b_hh1  = (const float*)d_in[8];
    const float* W_enc  = (const float*)d_in[9];
    const float* b_enc  = (const float*)d_in[10];
    float* out = (float*)d_out;

    float *p_Mtmp, *p_bias0, *p_bias0f, *p_bias1;
    __half *p_A1f, *p_B1fhi, *p_B1flo, *p_B2f;
    __half *p_H1f, *p_h0fA, *p_h0fB, *p_h1zf, *p_Wc0, *p_Wc1;
    cudaGetSymbolAddress((void**)&p_Mtmp,   g_Mtmp);
    cudaGetSymbolAddress((void**)&p_bias0,  g_bias0);
    cudaGetSymbolAddress((void**)&p_bias0f, g_bias0f);
    cudaGetSymbolAddress((void**)&p_bias1,  g_bias1);
    cudaGetSymbolAddress((void**)&p_A1f,    g_A1f);
    cudaGetSymbolAddress((void**)&p_B1fhi,  g_B1fhi);
    cudaGetSymbolAddress((void**)&p_B1flo,  g_B1flo);
    cudaGetSymbolAddress((void**)&p_B2f,    g_B2f);
    cudaGetSymbolAddress((void**)&p_H1f,    g_H1f);
    cudaGetSymbolAddress((void**)&p_h0fA,   g_h0fA);
    cudaGetSymbolAddress((void**)&p_h0fB,   g_h0fB);
    cudaGetSymbolAddress((void**)&p_h1zf,   g_h1zf);
    cudaGetSymbolAddress((void**)&p_Wc0,    g_Wc0);
    cudaGetSymbolAddress((void**)&p_Wc1,    g_Wc1);

    cudaFuncSetAttribute((const void*)gemm1_f16x2_kernel,
                         cudaFuncAttributeMaxDynamicSharedMemorySize, G1_SMEM);
    cudaFuncSetAttribute((const void*)gemm2_f16_kernel,
                         cudaFuncAttributeMaxDynamicSharedMemorySize, G2_SMEM);
    cudaFuncSetAttribute((const void*)lstm_persistent_kernel,
                         cudaFuncAttributeMaxDynamicSharedMemorySize, PERS_SMEM);

    // ---- prep ----
    prep_misc_kernel<<<(BB * DD + 255) / 256, 256>>>(input_, b_ih0, b_hh0, b_ih1, b_hh1);
    cudaMemsetAsync(p_Mtmp, 0, (size_t)GG * DD * sizeof(float));
    bfused_kernel<<<GG, 256>>>(W_ih0, b_enc);

    dim3 tb(32, 8);
    transpose_split_f16_kernel<<<dim3(DD / 32, (VV + 31) / 32), tb>>>(W_enc, p_B1fhi, p_B1flo);
    f32_to_f16_kernel<<<(GG * VV / 4 + 255) / 256, 256>>>(W_ih0, p_A1f, GG * VV);
    f32_to_f16_kernel<<<(VV * DD / 4 + 255) / 256, 256>>>(W_enc, p_B2f, VV * DD);

    // GEMM1: Mtmp += W_ih0 @ W_enc^T  [fp16 2-term, BM=256, split-K=2, 64 CTAs]
    gemm1_f16x2_kernel<<<dim3(DD / 128, GG / 256, 2), 512, G1_SMEM>>>(
        p_A1f, p_B1fhi, p_B1flo, p_Mtmp);

    // fused, gate-interleaved fp16 cell weights (single term)
    build_cell_w_kernel<<<2048, 256>>>(p_Mtmp, W_hh0, p_Wc0);
    build_cell_w_kernel<<<2048, 256>>>(W_ih1, W_hh1, p_Wc1);

    // ---- recurrence: one persistent launch, 64 CTAs ----
    lstm_persistent_kernel<<<NCTA, 256, PERS_SMEM>>>(
        p_Wc0, p_Wc1, p_h0fA, p_h0fB, p_h1zf, p_H1f,
        p_bias0, p_bias0f, p_bias1);

    // GEMM2: OUT(2560,10000) = H1f @ B2f^T + b_enc  [fp16 single-B]
    gemm2_f16_kernel<<<dim3((VV + 127) / 128, (TT * BB) / 256), 512, G2_SMEM>>>(
        p_H1f, p_B2f, out, b_enc, TT * BB, VV, DD);
}

// round 13
// speedup vs baseline: 1.2302x; 1.2302x over previous
#include <cuda_runtime.h>
#include <cuda_fp16.h>
#include <math.h>
#include <stdint.h>

#define BB 128     // batch
#define DD 512     // hidden
#define GG 2048    // 4*D
#define VV 10000   // vocab
#define TT 20      // timesteps
#define NCTA 64    // persistent kernel CTAs

// ---------------- device scratch (no allocation allowed) ----------------
__device__ float g_Mtmp[GG * DD];    // W_ih0 @ W_enc (fp32, split-K red target)
__device__ float g_bias0[GG];
__device__ float g_bias0f[GG];
__device__ float g_bias1[GG];
__device__ unsigned g_bar;
// fp16 operands for GEMM1
__device__ __half g_A1f[(size_t)GG * VV];          // W_ih0 (2048,10000) fp16
__device__ __half g_B1fhi[(size_t)DD * VV];        // W_enc^T (512,10000) fp16 hi/lo
__device__ __half g_B1flo[(size_t)DD * VV];
// fp16 operand for GEMM2
__device__ __half g_B2f[(size_t)VV * DD];          // W_enc (10000,512) fp16
// fp16 recurrence state
__device__ __half g_H1f[TT * BB * DD];
__device__ __half g_h0fA[BB * DD], g_h0fB[BB * DD];
__device__ __half g_h1zf[BB * DD];
// fused, gate-interleaved cell weights (fp16 single): rows n'=d*4+gate, K=1024=[x|h]
__device__ __half g_Wc0[(size_t)GG * 1024];
__device__ __half g_Wc1[(size_t)GG * 1024];

// =========================================================================
// helpers
// =========================================================================
__device__ __forceinline__ uint32_t smem_u32(const void* p) {
    uint32_t a;
    asm("{ .reg .u64 t; cvta.to.shared.u64 t, %1; cvt.u32.u64 %0, t; }" : "=r"(a) : "l"(p));
    return a;
}
#define SWZ128(o) ((o) ^ (((o) >> 3) & 0x70))

__device__ __forceinline__ void ldsm_x4(uint32_t* r, uint32_t addr) {
    asm volatile("ldmatrix.sync.aligned.m8n8.x4.shared.b16 {%0,%1,%2,%3}, [%4];"
                 : "=r"(r[0]), "=r"(r[1]), "=r"(r[2]), "=r"(r[3]) : "r"(addr));
}
__device__ __forceinline__ void mma16816h(float* d, const uint32_t* a, const uint32_t* b) {
    asm volatile(
        "mma.sync.aligned.m16n8k16.row.col.f32.f16.f16.f32 "
        "{%0,%1,%2,%3}, {%4,%5,%6,%7}, {%8,%9}, {%0,%1,%2,%3};"
        : "+f"(d[0]), "+f"(d[1]), "+f"(d[2]), "+f"(d[3])
        : "r"(a[0]), "r"(a[1]), "r"(a[2]), "r"(a[3]), "r"(b[0]), "r"(b[1]));
}
__device__ __forceinline__ void cp_async16(uint32_t daddr, const void* g, unsigned sz) {
    asm volatile("cp.async.cg.shared.global [%0], [%1], 16, %2;"
                 :: "r"(daddr), "l"(g), "r"(sz));
}
__device__ __forceinline__ void red_addf(float* p, float v) {
    asm volatile("red.global.add.f32 [%0], %1;" :: "l"(p), "f"(v) : "memory");
}
#define CP_COMMIT() asm volatile("cp.async.commit_group;" ::: "memory")
#define CP_WAIT(n)  asm volatile("cp.async.wait_group %0;" :: "n"(n) : "memory")

// =========================================================================
// prep kernels
// =========================================================================
__global__ void prep_misc_kernel(const float* __restrict__ input_,
                                 const float* __restrict__ b_ih0, const float* __restrict__ b_hh0,
                                 const float* __restrict__ b_ih1, const float* __restrict__ b_hh1) {
    int i = blockIdx.x * blockDim.x + threadIdx.x;
    if (i == 0) g_bar = 0u;
    if (i < GG) {
        g_bias0[i] = b_ih0[i] + b_hh0[i];
        g_bias1[i] = b_ih1[i] + b_hh1[i];
    }
    if (i < BB * DD) g_h1zf[i] = __float2half_rn(0.f);
    if (i < BB * DD / 4) {
        float4 v = *(const float4*)(input_ + i * 4);
        __half h[4] = {__float2half_rn(v.x), __float2half_rn(v.y),
                       __float2half_rn(v.z), __float2half_rn(v.w)};
        *(uint2*)(g_h0fA + i * 4) = *(uint2*)h;
    }
}

__global__ void bfused_kernel(const float* __restrict__ W_ih0, const float* __restrict__ b_enc) {
    __shared__ float red[256];
    int g = blockIdx.x;
    float s = 0.f;
    for (int v = threadIdx.x; v < VV; v += 256)
        s += W_ih0[(size_t)g * VV + v] * b_enc[v];
    red[threadIdx.x] = s;
    __syncthreads();
    for (int o = 128; o > 0; o >>= 1) {
        if (threadIdx.x < o) red[threadIdx.x] += red[threadIdx.x + o];
        __syncthreads();
    }
    if (threadIdx.x == 0) g_bias0f[g] = g_bias0[g] + red[0];
}

// W_enc (10000,512) fp32 -> B1fhi/B1flo (512,10000) fp16 (fused transpose + split)
__global__ void transpose_split_f16_kernel(const float* __restrict__ src,
                                           __half* __restrict__ hi,
                                           __half* __restrict__ lo) {
    __shared__ float tile[32][33];
    int c0 = blockIdx.x * 32;
    int r0 = blockIdx.y * 32;
    int c = c0 + threadIdx.x;
    for (int i = threadIdx.y; i < 32; i += 8) {
        int r = r0 + i;
        if (r < VV) tile[i][threadIdx.x] = src[(size_t)r * DD + c];
    }
    __syncthreads();
    int r = r0 + threadIdx.x;
    if (r < VV) {
        for (int i = threadIdx.y; i < 32; i += 8) {
            float v = tile[threadIdx.x][i];
            __half h = __float2half_rn(v);
            hi[(size_t)(c0 + i) * VV + r] = h;
            lo[(size_t)(c0 + i) * VV + r] = __float2half_rn(v - __half2float(h));
        }
    }
}

// fp32 -> fp16 single
__global__ void f32_to_f16_kernel(const float* __restrict__ src, __half* __restrict__ dst, int n) {
    int i = (blockIdx.x * blockDim.x + threadIdx.x) * 4;
    if (i < n) {
        float4 v = *(const float4*)(src + i);
        __half h[4] = {__float2half_rn(v.x), __float2half_rn(v.y),
                       __float2half_rn(v.z), __float2half_rn(v.w)};
        *(uint2*)(dst + i) = *(uint2*)h;
    }
}

// fused cell weights (fp16 single): out (2048,1024): n'=d*4+gate, src n=gate*512+d,
// k<512 from srcX else srcH. grid=2048, block=256.
__global__ void build_cell_w_kernel(const float* __restrict__ srcX, const float* __restrict__ srcH,
                                    __half* __restrict__ w) {
    int idx = blockIdx.x * 256 + threadIdx.x;
    int e = idx * 4;
    int np = e >> 10, k4 = e & 1023;
    int d = np >> 2, gate = np & 3;
    int n = gate * 512 + d;
    const float* s = (k4 < 512) ? (srcX + (size_t)n * 512 + k4)
                                : (srcH + (size_t)n * 512 + (k4 - 512));
    float4 v = *(const float4*)s;
    __half h[4] = {__float2half_rn(v.x), __float2half_rn(v.y),
                   __float2half_rn(v.z), __float2half_rn(v.w)};
    *(uint2*)(w + (size_t)np * 1024 + k4) = *(uint2*)h;
}

// =========================================================================
// GEMM1 (fp16 2-term, split-K=4): Mtmp(2048,512) += A(2048,10000)f16 @ (Bhi+Blo)(512,10000)^T
// BM=256 (512 thr, 8m x 2n warps), BN=128, BK=64. grid (4, 8, 4) = 128 CTAs.
// KSPLIT=2560 (64-aligned => 16B-aligned global starts; last split is 2320, guarded).
// smem/buf: A 32K | Bhi 16K | Blo 16K = 64K; x2 = 128K.
// =========================================================================
#define G1_BUF 65536
#define G1_SMEM (2 * G1_BUF)
#define KSPLIT 2560

__global__ __launch_bounds__(512) void gemm1_f16x2_kernel(
    const __half* __restrict__ A,
    const __half* __restrict__ Bhi, const __half* __restrict__ Blo,
    float* __restrict__ C)
{
    extern __shared__ char smem[];
    const uint32_t sb = smem_u32(smem);
    const int tid = threadIdx.x, wid = tid >> 5, lane = tid & 31;
    const int wm = wid & 7, wn = wid >> 3;
    const int m0 = blockIdx.y * 256, n0 = blockIdx.x * 128;
    const int kb0 = blockIdx.z * KSPLIT;
    const int kend = min(kb0 + KSPLIT, VV);
    const int NT = (kend - kb0 + 63) / 64;

    float acc[2][8][4];
    #pragma unroll
    for (int mt = 0; mt < 2; mt++)
        #pragma unroll
        for (int nt = 0; nt < 8; nt++)
            #pragma unroll
            for (int j = 0; j < 4; j++) acc[mt][nt][j] = 0.f;

    auto load_chunk = [&](int kt, int buf) {
        const int kc = kb0 + kt * 64;
        const uint32_t bufbase = sb + buf * G1_BUF;
        #pragma unroll
        for (int it = 0; it < 4; it++) {
            int i = it * 512 + tid;
            int r = i >> 3, c16 = i & 7;
            int gk = kc + c16 * 8;
            bool inb = gk < kend;
            cp_async16(bufbase + SWZ128(r * 128 + c16 * 16),
                       A + (inb ? ((size_t)(m0 + r) * VV + gk) : 0), inb ? 16u : 0u);
        }
        #pragma unroll
        for (int w = 0; w < 2; w++) {
            const __half* src = w ? Blo : Bhi;
            uint32_t tdst = bufbase + 32768 + w * 16384;
            #pragma unroll
            for (int it = 0; it < 2; it++) {
                int i = it * 512 + tid;
                int r = i >> 3, c16 = i & 7;
                int gk = kc + c16 * 8;
                bool inb = gk < kend;
                cp_async16(tdst + SWZ128(r * 128 + c16 * 16),
                           src + (inb ? ((size_t)(n0 + r) * VV + gk) : 0), inb ? 16u : 0u);
            }
        }
        CP_COMMIT();
    };

    load_chunk(0, 0);
    const int g8 = lane >> 3, rg = lane & 7;

    for (int kt = 0; kt < NT; kt++) {
        const int buf = kt & 1;
        if (kt + 1 < NT) { load_chunk(kt + 1, buf ^ 1); CP_WAIT(1); }
        else             { CP_WAIT(0); }
        __syncthreads();

        const uint32_t bA = sb + buf * G1_BUF;
        const uint32_t bBh = bA + 32768;
        const uint32_t bBl = bA + 49152;

        #pragma unroll
        for (int kk = 0; kk < 4; kk++) {
            const int kb = kk * 32;
            uint32_t a4[2][4], bh[8][2], bl[8][2];
            #pragma unroll
            for (int mt = 0; mt < 2; mt++) {
                int row = wm * 32 + mt * 16 + (g8 & 1) * 8 + rg;
                ldsm_x4(a4[mt], bA + SWZ128(row * 128 + kb + (g8 >> 1) * 16));
            }
            #pragma unroll
            for (int p = 0; p < 4; p++) {
                int rowb = wn * 64 + p * 16 + (g8 >> 1) * 8 + rg;
                uint32_t off = SWZ128(rowb * 128 + kb + (g8 & 1) * 16);
                uint32_t t[4];
                ldsm_x4(t, bBh + off);
                bh[2 * p][0] = t[0]; bh[2 * p][1] = t[1];
                bh[2 * p + 1][0] = t[2]; bh[2 * p + 1][1] = t[3];
                ldsm_x4(t, bBl + off);
                bl[2 * p][0] = t[0]; bl[2 * p][1] = t[1];
                bl[2 * p + 1][0] = t[2]; bl[2 * p + 1][1] = t[3];
            }
            #pragma unroll
            for (int mt = 0; mt < 2; mt++)
                #pragma unroll
                for (int nt = 0; nt < 8; nt++) {
                    mma16816h(acc[mt][nt], a4[mt], bh[nt]);
                    mma16816h(acc[mt][nt], a4[mt], bl[nt]);
                }
        }
        __syncthreads();
    }

    // split-K reduction epilogue
    #pragma unroll
    for (int mt = 0; mt < 2; mt++) {
        int row = m0 + wm * 32 + mt * 16 + (lane >> 2);
        #pragma unroll
        for (int nt = 0; nt < 8; nt++) {
            int col = n0 + wn * 64 + nt * 8 + (lane & 3) * 2;
            float* p0 = &C[(size_t)row * DD + col];
            float* p1 = &C[(size_t)(row + 8) * DD + col];
            red_addf(p0, acc[mt][nt][0]);
            red_addf(p0 + 1, acc[mt][nt][1]);
            red_addf(p1, acc[mt][nt][2]);
            red_addf(p1 + 1, acc[mt][nt][3]);
        }
    }
}

// =========================================================================
// GEMM2 (fp16 single-B): OUT(M,N) = A(M,K)f16 @ B(N,K)^T + bias.
// BM=256, BN=128, BK=64; 512 threads (8m x 2n warps).
// smem/buf: A 32K | B 16K = 48K; x2 = 96K.
// =========================================================================
#define G2_BUF 49152
#define G2_SMEM (2 * G2_BUF)

__global__ __launch_bounds__(512) void gemm2_f16_kernel(
    const __half* __restrict__ A, const __half* __restrict__ B,
    float* __restrict__ C, const float* __restrict__ bias,
    int Mtot, int Ntot, int Ktot)
{
    extern __shared__ char smem[];
    const uint32_t sb = smem_u32(smem);
    const int tid = threadIdx.x, wid = tid >> 5, lane = tid & 31;
    const int wm = wid & 7, wn = wid >> 3;
    const int m0 = blockIdx.y * 256, n0 = blockIdx.x * 128;
    const int NT = (Ktot + 63) / 64;

    float acc[2][8][4];
    #pragma unroll
    for (int mt = 0; mt < 2; mt++)
        #pragma unroll
        for (int nt = 0; nt < 8; nt++)
            #pragma unroll
            for (int j = 0; j < 4; j++) acc[mt][nt][j] = 0.f;

    auto load_chunk = [&](int kt, int buf) {
        const int kc = kt * 64;
        const uint32_t bufbase = sb + buf * G2_BUF;
        #pragma unroll
        for (int it = 0; it < 4; it++) {
            int i = it * 512 + tid;
            int r = i >> 3, c16 = i & 7;
            cp_async16(bufbase + SWZ128(r * 128 + c16 * 16),
                       A + (size_t)(m0 + r) * Ktot + kc + c16 * 8, 16);
        }
        #pragma unroll
        for (int it = 0; it < 2; it++) {
            int i = it * 512 + tid;
            int r = i >> 3, c16 = i & 7;
            int gr = n0 + r;
            bool inb = gr < Ntot;
            cp_async16(bufbase + 32768 + SWZ128(r * 128 + c16 * 16),
                       B + (inb ? ((size_t)gr * Ktot + kc + c16 * 8) : 0), inb ? 16u : 0u);
        }
        CP_COMMIT();
    };

    load_chunk(0, 0);
    const int g8 = lane >> 3, rg = lane & 7;

    for (int kt = 0; kt < NT; kt++) {
        const int buf = kt & 1;
        if (kt + 1 < NT) { load_chunk(kt + 1, buf ^ 1); CP_WAIT(1); }
        else             { CP_WAIT(0); }
        __syncthreads();

        const uint32_t bA = sb + buf * G2_BUF;
        const uint32_t bB = bA + 32768;

        #pragma unroll
        for (int kk = 0; kk < 4; kk++) {
            const int kb = kk * 32;
            uint32_t a4[2][4], b[8][2];
            #pragma unroll
            for (int mt = 0; mt < 2; mt++) {
                int row = wm * 32 + mt * 16 + (g8 & 1) * 8 + rg;
                ldsm_x4(a4[mt], bA + SWZ128(row * 128 + kb + (g8 >> 1) * 16));
            }
            #pragma unroll
            for (int p = 0; p < 4; p++) {
                int rowb = wn * 64 + p * 16 + (g8 >> 1) * 8 + rg;
                uint32_t t[4];
                ldsm_x4(t, bB + SWZ128(rowb * 128 + kb + (g8 & 1) * 16));
                b[2 * p][0] = t[0]; b[2 * p][1] = t[1];
                b[2 * p + 1][0] = t[2]; b[2 * p + 1][1] = t[3];
            }
            #pragma unroll
            for (int mt = 0; mt < 2; mt++)
                #pragma unroll
                for (int nt = 0; nt < 8; nt++)
                    mma16816h(acc[mt][nt], a4[mt], b[nt]);
        }
        __syncthreads();
    }

    #pragma unroll
    for (int mt = 0; mt < 2; mt++) {
        int row = m0 + wm * 32 + mt * 16 + (lane >> 2);
        #pragma unroll
        for (int nt = 0; nt < 8; nt++) {
            int col = n0 + wn * 64 + nt * 8 + (lane & 3) * 2;
            if (col < Ntot) {
                float b0 = bias[col], b1 = bias[col + 1];
                float2 v0 = make_float2(acc[mt][nt][0] + b0, acc[mt][nt][1] + b1);
                float2 v1 = make_float2(acc[mt][nt][2] + b0, acc[mt][nt][3] + b1);
                *(float2*)&C[(size_t)row * Ntot + col] = v0;
                *(float2*)&C[(size_t)(row + 8) * Ntot + col] = v1;
            }
        }
    }
}

// =========================================================================
// persistent LSTM recurrence, fp16 single-W, 64 CTAs x 32 gate rows.
// CTA b owns gate rows n0 = b*32 (d in [b*8, b*8+8)); 256 threads (8 warps).
// smem: W0 64K | W1 64K | A 3x16K | gates 128x33 f32 ~16.5K
// =========================================================================
#define PSM_W0 0
#define PSM_W1 65536
#define PSM_A  131072
#define PSM_G  180224
#define GSTRIDE 33
#define PERS_SMEM (180224 + 128 * GSTRIDE * 4)

__global__ __launch_bounds__(256) void lstm_persistent_kernel(
    const __half* __restrict__ Wc0, const __half* __restrict__ Wc1,
    __half* __restrict__ h0fA, __half* __restrict__ h0fB,
    const __half* __restrict__ h1zf, __half* __restrict__ H1f,
    const float* __restrict__ bias0, const float* __restrict__ bias0f,
    const float* __restrict__ bias1)
{
    extern __shared__ char smem[];
    const uint32_t sb = smem_u32(smem);
    float* gates = (float*)(smem + PSM_G);
    const int tid = threadIdx.x, wid = tid >> 5, lane = tid & 31;
    const int n0 = blockIdx.x * 32;
    const int g8 = lane >> 3, rg = lane & 7;

    // persistent weight slices: per layer 16 chunks x (32 rows x 128B) = 64KB
    #pragma unroll
    for (int L = 0; L < 2; L++) {
        const __half* src = L ? Wc1 : Wc0;
        const uint32_t dstb = L ? PSM_W1 : PSM_W0;
        #pragma unroll
        for (int it = 0; it < 16; it++) {
            int i = it * 256 + tid;
            int ch = i >> 8, r = (i >> 3) & 31, c16 = i & 7;
            cp_async16(sb + dstb + ch * 4096 + SWZ128(r * 128 + c16 * 16),
                       src + (size_t)(n0 + r) * 1024 + ch * 64 + c16 * 8, 16);
        }
    }
    CP_COMMIT();

    float rb0[4][4], rb0f[4][4], rb1[4][4];
    #pragma unroll
    for (int it = 0; it < 4; it++) {
        int idx = it * 256 + tid;
        int dd = idx & 7;
        int d = blockIdx.x * 8 + dd;
        #pragma unroll
        for (int g = 0; g < 4; g++) {
            rb0[it][g]  = bias0[g * 512 + d];
            rb0f[it][g] = bias0f[g * 512 + d];
            rb1[it][g]  = bias1[g * 512 + d];
        }
    }

    float c0r[4] = {0.f, 0.f, 0.f, 0.f}, c1r[4] = {0.f, 0.f, 0.f, 0.f};
    unsigned epoch = 0;
    int cur = 0;

    for (int t = 0; t < TT; t++) {
        #pragma unroll
        for (int layer = 0; layer < 2; layer++) {
            const __half *xf, *hf;
            int kstart;
            if (layer == 0) {
                kstart = (t == 0) ? 8 : 0;
                xf = (t == 0) ? (const __half*)0 : H1f + (size_t)(t - 1) * BB * DD;
                hf = cur ? h0fB : h0fA;
            } else {
                kstart = 0;
                xf = cur ? h0fA : h0fB;
                hf = (t == 0) ? h1zf : H1f + (size_t)(t - 1) * BB * DD;
            }
            const uint32_t wbase = sb + (layer ? PSM_W1 : PSM_W0);

            auto load_chunk = [&](int ch, int buf) {
                const __half* src = (ch < 8) ? xf : hf;
                int koff = (ch & 7) * 64;
                const uint32_t base = sb + PSM_A + buf * 16384;
                #pragma unroll
                for (int it = 0; it < 4; it++) {
                    int i = it * 256 + tid;
                    int r = i >> 3, c16 = i & 7;
                    cp_async16(base + SWZ128(r * 128 + c16 * 16),
                               src + (size_t)r * 512 + koff + c16 * 8, 16);
                }
                CP_COMMIT();
            };

            float acc[4][4];
            #pragma unroll
            for (int b = 0; b < 4; b++)
                #pragma unroll
                for (int j = 0; j < 4; j++) acc[b][j] = 0.f;

            load_chunk(kstart, 0);
            if (kstart + 1 < 16) load_chunk(kstart + 1, 1);
            for (int ch = kstart; ch < 16; ch++) {
                const int i = ch - kstart;
                if (ch + 1 < 16) { CP_WAIT(1); }
                else             { CP_WAIT(0); }
                __syncthreads();
                if (ch + 2 < 16) load_chunk(ch + 2, (i + 2) % 3);

                const uint32_t bA = sb + PSM_A + (i % 3) * 16384;
                const uint32_t bW = wbase + ch * 4096;

                #pragma unroll
                for (int kk = 0; kk < 4; kk++) {
                    const int kb = kk * 32;
                    uint32_t a4[4], t[4], t2[4];
                    int row = wid * 16 + (g8 & 1) * 8 + rg;
                    ldsm_x4(a4, bA + SWZ128(row * 128 + kb + (g8 >> 1) * 16));
                    int rowb = (g8 >> 1) * 8 + rg;
                    uint32_t offc = kb + (g8 & 1) * 16;
                    ldsm_x4(t,  bW + SWZ128(rowb * 128 + offc));
                    ldsm_x4(t2, bW + SWZ128((rowb + 16) * 128 + offc));
                    uint32_t b0[2] = {t[0], t[1]},  b1[2] = {t[2], t[3]};
                    uint32_t b2[2] = {t2[0], t2[1]}, b3[2] = {t2[2], t2[3]};
                    mma16816h(acc[0], a4, b0);
                    mma16816h(acc[1], a4, b1);
                    mma16816h(acc[2], a4, b2);
                    mma16816h(acc[3], a4, b3);
                }
            }
            __syncthreads();

            // stage gates (128 rows x 32 cols, stride 33 vs bank conflicts)
            {
                int r0 = wid * 16 + (lane >> 2);
                int cb = (lane & 3) * 2;
                #pragma unroll
                for (int b = 0; b < 4; b++) {
                    gates[r0 * GSTRIDE + b * 8 + cb]           = acc[b][0];
                    gates[r0 * GSTRIDE + b * 8 + cb + 1]       = acc[b][1];
                    gates[(r0 + 8) * GSTRIDE + b * 8 + cb]     = acc[b][2];
                    gates[(r0 + 8) * GSTRIDE + b * 8 + cb + 1] = acc[b][3];
                }
            }
            __syncthreads();

            __half* of = (layer == 0) ? (cur ? h0fA : h0fB) : (H1f + (size_t)t * BB * DD);
            #pragma unroll
            for (int it = 0; it < 4; it++) {
                int idx = it * 256 + tid;
                int row = idx >> 3, dd = idx & 7;
                int d = blockIdx.x * 8 + dd;
                const float* rb = (layer == 0) ? ((t == 0) ? rb0[it] : rb0f[it]) : rb1[it];
                float gi = gates[row * GSTRIDE + dd * 4 + 0] + rb[0];
                float gf = gates[row * GSTRIDE + dd * 4 + 1] + rb[1];
                float gg = gates[row * GSTRIDE + dd * 4 + 2] + rb[2];
                float go = gates[row * GSTRIDE + dd * 4 + 3] + rb[3];
                float i_ = 1.f / (1.f + expf(-gi));
                float f_ = 1.f / (1.f + expf(-gf));
                float g_ = tanhf(gg);
                float o_ = 1.f / (1.f + expf(-go));
                float* cr = (layer == 0) ? &c0r[it] : &c1r[it];
                float cn = f_ * (*cr) + i_ * g_;
                *cr = cn;
                of[row * 512 + d] = __float2half_rn(o_ * tanhf(cn));
            }

            __threadfence();
            __syncthreads();
            epoch++;
            if (tid == 0) {
                atomicAdd(&g_bar, 1u);
                unsigned target = epoch * NCTA;
                volatile unsigned* p = &g_bar;
                while (*p < target) { }
                __threadfence();
            }
            __syncthreads();
        }
        cur ^= 1;
    }
}

// =========================================================================
// host
// =========================================================================
extern "C" void kernel_launch(void* const* d_in, const int* in_sizes, int n_in,
                              void* d_out, int out_size) {
    const float* input_ = (const float*)d_in[0];
    const float* W_ih0  = (const float*)d_in[1];
    const float* W_hh0  = (const float*)d_in[2];
    const float* b_ih0  = (const float*)d_in[3];
    const float* b_hh0  = (const float*)d_in[4];
    const float* W_ih1  = (const float*)d_in[5];
    const float* W_hh1  = (const float*)d_in[6];
    const float* b_ih1  = (const float*)d_in[7];
    const float* b_hh1  = (const float*)d_in[8];
    const float* W_enc  = (const float*)d_in[9];
    const float* b_enc  = (const float*)d_in[10];
    float* out = (float*)d_out;

    float *p_Mtmp, *p_bias0, *p_bias0f, *p_bias1;
    __half *p_A1f, *p_B1fhi, *p_B1flo, *p_B2f;
    __half *p_H1f, *p_h0fA, *p_h0fB, *p_h1zf, *p_Wc0, *p_Wc1;
    cudaGetSymbolAddress((void**)&p_Mtmp,   g_Mtmp);
    cudaGetSymbolAddress((void**)&p_bias0,  g_bias0);
    cudaGetSymbolAddress((void**)&p_bias0f, g_bias0f);
    cudaGetSymbolAddress((void**)&p_bias1,  g_bias1);
    cudaGetSymbolAddress((void**)&p_A1f,    g_A1f);
    cudaGetSymbolAddress((void**)&p_B1fhi,  g_B1fhi);
    cudaGetSymbolAddress((void**)&p_B1flo,  g_B1flo);
    cudaGetSymbolAddress((void**)&p_B2f,    g_B2f);
    cudaGetSymbolAddress((void**)&p_H1f,    g_H1f);
    cudaGetSymbolAddress((void**)&p_h0fA,   g_h0fA);
    cudaGetSymbolAddress((void**)&p_h0fB,   g_h0fB);
    cudaGetSymbolAddress((void**)&p_h1zf,   g_h1zf);
    cudaGetSymbolAddress((void**)&p_Wc0,    g_Wc0);
    cudaGetSymbolAddress((void**)&p_Wc1,    g_Wc1);

    cudaFuncSetAttribute((const void*)gemm1_f16x2_kernel,
                         cudaFuncAttributeMaxDynamicSharedMemorySize, G1_SMEM);
    cudaFuncSetAttribute((const void*)gemm2_f16_kernel,
                         cudaFuncAttributeMaxDynamicSharedMemorySize, G2_SMEM);
    cudaFuncSetAttribute((const void*)lstm_persistent_kernel,
                         cudaFuncAttributeMaxDynamicSharedMemorySize, PERS_SMEM);

    // ---- prep ----
    prep_misc_kernel<<<(BB * DD + 255) / 256, 256>>>(input_, b_ih0, b_hh0, b_ih1, b_hh1);
    cudaMemsetAsync(p_Mtmp, 0, (size_t)GG * DD * sizeof(float));
    bfused_kernel<<<GG, 256>>>(W_ih0, b_enc);

    dim3 tb(32, 8);
    transpose_split_f16_kernel<<<dim3(DD / 32, (VV + 31) / 32), tb>>>(W_enc, p_B1fhi, p_B1flo);
    f32_to_f16_kernel<<<(GG * VV / 4 + 255) / 256, 256>>>(W_ih0, p_A1f, GG * VV);
    f32_to_f16_kernel<<<(VV * DD / 4 + 255) / 256, 256>>>(W_enc, p_B2f, VV * DD);

    // GEMM1: Mtmp += W_ih0 @ W_enc^T  [fp16 2-term, BM=256, split-K=4, 128 CTAs]
    gemm1_f16x2_kernel<<<dim3(DD / 128, GG / 256, 4), 512, G1_SMEM>>>(
        p_A1f, p_B1fhi, p_B1flo, p_Mtmp);

    // fused, gate-interleaved fp16 cell weights (single term)
    build_cell_w_kernel<<<2048, 256>>>(p_Mtmp, W_hh0, p_Wc0);
    build_cell_w_kernel<<<2048, 256>>>(W_ih1, W_hh1, p_Wc1);

    // ---- recurrence: one persistent launch, 64 CTAs ----
    lstm_persistent_kernel<<<NCTA, 256, PERS_SMEM>>>(
        p_Wc0, p_Wc1, p_h0fA, p_h0fB, p_h1zf, p_H1f,
        p_bias0, p_bias0f, p_bias1);

    // GEMM2: OUT(2560,10000) = H1f @ B2f^T + b_enc  [fp16 single-B]
    gemm2_f16_kernel<<<dim3((VV + 127) / 128, (TT * BB) / 256), 512, G2_SMEM>>>(
        p_H1f, p_B2f, out, b_enc, TT * BB, VV, DD);
}

// round 14
// speedup vs baseline: 1.3945x; 1.1336x over previous
#include <cuda_runtime.h>
#include <cuda_fp16.h>
#include <math.h>
#include <stdint.h>

#define BB 128     // batch
#define DD 512     // hidden
#define GG 2048    // 4*D
#define VV 10000   // vocab
#define TT 20      // timesteps
#define NCTA 64    // persistent kernel CTAs

// ---------------- device scratch (no allocation allowed) ----------------
__device__ float g_Mtmp[GG * DD];    // W_ih0 @ W_enc (fp32, split-K red target)
__device__ float g_bias0[GG];
__device__ float g_bias0f[GG];
__device__ float g_bias1[GG];
__device__ unsigned g_bar;
// fp16 operands for GEMM1 (all single-term)
__device__ __half g_A1f[(size_t)GG * VV];          // W_ih0 (2048,10000) fp16
__device__ __half g_B1f[(size_t)DD * VV];          // W_enc^T (512,10000) fp16
// fp16 operand for GEMM2
__device__ __half g_B2f[(size_t)VV * DD];          // W_enc (10000,512) fp16
// fp16 recurrence state
__device__ __half g_H1f[TT * BB * DD];
__device__ __half g_h0fA[BB * DD], g_h0fB[BB * DD];
__device__ __half g_h1zf[BB * DD];
// fused, gate-interleaved cell weights (fp16 single): rows n'=d*4+gate, K=1024=[x|h]
__device__ __half g_Wc0[(size_t)GG * 1024];
__device__ __half g_Wc1[(size_t)GG * 1024];

// =========================================================================
// helpers
// =========================================================================
__device__ __forceinline__ uint32_t smem_u32(const void* p) {
    uint32_t a;
    asm("{ .reg .u64 t; cvta.to.shared.u64 t, %1; cvt.u32.u64 %0, t; }" : "=r"(a) : "l"(p));
    return a;
}
#define SWZ128(o) ((o) ^ (((o) >> 3) & 0x70))

__device__ __forceinline__ void ldsm_x4(uint32_t* r, uint32_t addr) {
    asm volatile("ldmatrix.sync.aligned.m8n8.x4.shared.b16 {%0,%1,%2,%3}, [%4];"
                 : "=r"(r[0]), "=r"(r[1]), "=r"(r[2]), "=r"(r[3]) : "r"(addr));
}
__device__ __forceinline__ void mma16816h(float* d, const uint32_t* a, const uint32_t* b) {
    asm volatile(
        "mma.sync.aligned.m16n8k16.row.col.f32.f16.f16.f32 "
        "{%0,%1,%2,%3}, {%4,%5,%6,%7}, {%8,%9}, {%0,%1,%2,%3};"
        : "+f"(d[0]), "+f"(d[1]), "+f"(d[2]), "+f"(d[3])
        : "r"(a[0]), "r"(a[1]), "r"(a[2]), "r"(a[3]), "r"(b[0]), "r"(b[1]));
}
__device__ __forceinline__ void cp_async16(uint32_t daddr, const void* g, unsigned sz) {
    asm volatile("cp.async.cg.shared.global [%0], [%1], 16, %2;"
                 :: "r"(daddr), "l"(g), "r"(sz));
}
__device__ __forceinline__ void red_addf(float* p, float v) {
    asm volatile("red.global.add.f32 [%0], %1;" :: "l"(p), "f"(v) : "memory");
}
#define CP_COMMIT() asm volatile("cp.async.commit_group;" ::: "memory")
#define CP_WAIT(n)  asm volatile("cp.async.wait_group %0;" :: "n"(n) : "memory")

// =========================================================================
// prep kernels
// =========================================================================
__global__ void prep_misc_kernel(const float* __restrict__ input_,
                                 const float* __restrict__ b_ih0, const float* __restrict__ b_hh0,
                                 const float* __restrict__ b_ih1, const float* __restrict__ b_hh1) {
    int i = blockIdx.x * blockDim.x + threadIdx.x;
    if (i == 0) g_bar = 0u;
    if (i < GG) {
        g_bias0[i] = b_ih0[i] + b_hh0[i];
        g_bias1[i] = b_ih1[i] + b_hh1[i];
    }
    if (i < BB * DD) g_h1zf[i] = __float2half_rn(0.f);
    if (i < BB * DD / 4) {
        float4 v = *(const float4*)(input_ + i * 4);
        __half h[4] = {__float2half_rn(v.x), __float2half_rn(v.y),
                       __float2half_rn(v.z), __float2half_rn(v.w)};
        *(uint2*)(g_h0fA + i * 4) = *(uint2*)h;
    }
}

// fused: A1f = fp16(W_ih0)  AND  bias0f[g] = bias0[g] + W_ih0[g,:]·b_enc
// grid = 2048 (one row each), block = 256.
__global__ void conv_a1_bias_kernel(const float* __restrict__ W_ih0,
                                    const float* __restrict__ b_enc) {
    __shared__ float red[256];
    int g = blockIdx.x;
    const float* src = W_ih0 + (size_t)g * VV;
    __half* dst = g_A1f + (size_t)g * VV;
    float s = 0.f;
    for (int v4 = threadIdx.x * 4; v4 < VV; v4 += 1024) {
        float4 v = *(const float4*)(src + v4);
        __half h[4] = {__float2half_rn(v.x), __float2half_rn(v.y),
                       __float2half_rn(v.z), __float2half_rn(v.w)};
        *(uint2*)(dst + v4) = *(uint2*)h;
        float4 b = *(const float4*)(b_enc + v4);
        s += v.x * b.x + v.y * b.y + v.z * b.z + v.w * b.w;
    }
    red[threadIdx.x] = s;
    __syncthreads();
    for (int o = 128; o > 0; o >>= 1) {
        if (threadIdx.x < o) red[threadIdx.x] += red[threadIdx.x + o];
        __syncthreads();
    }
    if (threadIdx.x == 0) g_bias0f[g] = g_bias0[g] + red[0];
}

// W_enc (10000,512) fp32 -> B1f (512,10000) fp16 (fused transpose + convert)
__global__ void transpose_f16_kernel(const float* __restrict__ src, __half* __restrict__ dst) {
    __shared__ float tile[32][33];
    int c0 = blockIdx.x * 32;
    int r0 = blockIdx.y * 32;
    int c = c0 + threadIdx.x;
    for (int i = threadIdx.y; i < 32; i += 8) {
        int r = r0 + i;
        if (r < VV) tile[i][threadIdx.x] = src[(size_t)r * DD + c];
    }
    __syncthreads();
    int r = r0 + threadIdx.x;
    if (r < VV) {
        for (int i = threadIdx.y; i < 32; i += 8)
            dst[(size_t)(c0 + i) * VV + r] = __float2half_rn(tile[threadIdx.x][i]);
    }
}

// fp32 -> fp16 single
__global__ void f32_to_f16_kernel(const float* __restrict__ src, __half* __restrict__ dst, int n) {
    int i = (blockIdx.x * blockDim.x + threadIdx.x) * 4;
    if (i < n) {
        float4 v = *(const float4*)(src + i);
        __half h[4] = {__float2half_rn(v.x), __float2half_rn(v.y),
                       __float2half_rn(v.z), __float2half_rn(v.w)};
        *(uint2*)(dst + i) = *(uint2*)h;
    }
}

// fused cell weights (fp16 single): out (2048,1024): n'=d*4+gate, src n=gate*512+d,
// k<512 from srcX else srcH. grid=2048, block=256.
__global__ void build_cell_w_kernel(const float* __restrict__ srcX, const float* __restrict__ srcH,
                                    __half* __restrict__ w) {
    int idx = blockIdx.x * 256 + threadIdx.x;
    int e = idx * 4;
    int np = e >> 10, k4 = e & 1023;
    int d = np >> 2, gate = np & 3;
    int n = gate * 512 + d;
    const float* s = (k4 < 512) ? (srcX + (size_t)n * 512 + k4)
                                : (srcH + (size_t)n * 512 + (k4 - 512));
    float4 v = *(const float4*)s;
    __half h[4] = {__float2half_rn(v.x), __float2half_rn(v.y),
                   __float2half_rn(v.z), __float2half_rn(v.w)};
    *(uint2*)(w + (size_t)np * 1024 + k4) = *(uint2*)h;
}

// =========================================================================
// GEMM1 (fp16 single, split-K=4): Mtmp(2048,512) += A(2048,10000)f16 @ B(512,10000)^T
// BM=256 (512 thr, 8m x 2n warps), BN=128, BK=64. grid (4, 8, 4) = 128 CTAs.
// KSPLIT=2560 (64-aligned). smem/buf: A 32K | B 16K = 48K; x2 = 96K.
// =========================================================================
#define G1_BUF 49152
#define G1_SMEM (2 * G1_BUF)
#define KSPLIT 2560

__global__ __launch_bounds__(512) void gemm1_f16_kernel(
    const __half* __restrict__ A, const __half* __restrict__ B,
    float* __restrict__ C)
{
    extern __shared__ char smem[];
    const uint32_t sb = smem_u32(smem);
    const int tid = threadIdx.x, wid = tid >> 5, lane = tid & 31;
    const int wm = wid & 7, wn = wid >> 3;
    const int m0 = blockIdx.y * 256, n0 = blockIdx.x * 128;
    const int kb0 = blockIdx.z * KSPLIT;
    const int kend = min(kb0 + KSPLIT, VV);
    const int NT = (kend - kb0 + 63) / 64;

    float acc[2][8][4];
    #pragma unroll
    for (int mt = 0; mt < 2; mt++)
        #pragma unroll
        for (int nt = 0; nt < 8; nt++)
            #pragma unroll
            for (int j = 0; j < 4; j++) acc[mt][nt][j] = 0.f;

    auto load_chunk = [&](int kt, int buf) {
        const int kc = kb0 + kt * 64;
        const uint32_t bufbase = sb + buf * G1_BUF;
        #pragma unroll
        for (int it = 0; it < 4; it++) {
            int i = it * 512 + tid;
            int r = i >> 3, c16 = i & 7;
            int gk = kc + c16 * 8;
            bool inb = gk < kend;
            cp_async16(bufbase + SWZ128(r * 128 + c16 * 16),
                       A + (inb ? ((size_t)(m0 + r) * VV + gk) : 0), inb ? 16u : 0u);
        }
        #pragma unroll
        for (int it = 0; it < 2; it++) {
            int i = it * 512 + tid;
            int r = i >> 3, c16 = i & 7;
            int gk = kc + c16 * 8;
            bool inb = gk < kend;
            cp_async16(bufbase + 32768 + SWZ128(r * 128 + c16 * 16),
                       B + (inb ? ((size_t)(n0 + r) * VV + gk) : 0), inb ? 16u : 0u);
        }
        CP_COMMIT();
    };

    load_chunk(0, 0);
    const int g8 = lane >> 3, rg = lane & 7;

    for (int kt = 0; kt < NT; kt++) {
        const int buf = kt & 1;
        if (kt + 1 < NT) { load_chunk(kt + 1, buf ^ 1); CP_WAIT(1); }
        else             { CP_WAIT(0); }
        __syncthreads();

        const uint32_t bA = sb + buf * G1_BUF;
        const uint32_t bB = bA + 32768;

        #pragma unroll
        for (int kk = 0; kk < 4; kk++) {
            const int kb = kk * 32;
            uint32_t a4[2][4], b[8][2];
            #pragma unroll
            for (int mt = 0; mt < 2; mt++) {
                int row = wm * 32 + mt * 16 + (g8 & 1) * 8 + rg;
                ldsm_x4(a4[mt], bA + SWZ128(row * 128 + kb + (g8 >> 1) * 16));
            }
            #pragma unroll
            for (int p = 0; p < 4; p++) {
                int rowb = wn * 64 + p * 16 + (g8 >> 1) * 8 + rg;
                uint32_t t[4];
                ldsm_x4(t, bB + SWZ128(rowb * 128 + kb + (g8 & 1) * 16));
                b[2 * p][0] = t[0]; b[2 * p][1] = t[1];
                b[2 * p + 1][0] = t[2]; b[2 * p + 1][1] = t[3];
            }
            #pragma unroll
            for (int mt = 0; mt < 2; mt++)
                #pragma unroll
                for (int nt = 0; nt < 8; nt++)
                    mma16816h(acc[mt][nt], a4[mt], b[nt]);
        }
        __syncthreads();
    }

    // split-K reduction epilogue
    #pragma unroll
    for (int mt = 0; mt < 2; mt++) {
        int row = m0 + wm * 32 + mt * 16 + (lane >> 2);
        #pragma unroll
        for (int nt = 0; nt < 8; nt++) {
            int col = n0 + wn * 64 + nt * 8 + (lane & 3) * 2;
            float* p0 = &C[(size_t)row * DD + col];
            float* p1 = &C[(size_t)(row + 8) * DD + col];
            red_addf(p0, acc[mt][nt][0]);
            red_addf(p0 + 1, acc[mt][nt][1]);
            red_addf(p1, acc[mt][nt][2]);
            red_addf(p1 + 1, acc[mt][nt][3]);
        }
    }
}

// =========================================================================
// GEMM2 (fp16 single-B): OUT(M,N) = A(M,K)f16 @ B(N,K)^T + bias.
// BM=256, BN=128, BK=64; 512 threads (8m x 2n warps).
// smem/buf: A 32K | B 16K = 48K; x2 = 96K.
// =========================================================================
#define G2_BUF 49152
#define G2_SMEM (2 * G2_BUF)

__global__ __launch_bounds__(512) void gemm2_f16_kernel(
    const __half* __restrict__ A, const __half* __restrict__ B,
    float* __restrict__ C, const float* __restrict__ bias,
    int Mtot, int Ntot, int Ktot)
{
    extern __shared__ char smem[];
    const uint32_t sb = smem_u32(smem);
    const int tid = threadIdx.x, wid = tid >> 5, lane = tid & 31;
    const int wm = wid & 7, wn = wid >> 3;
    const int m0 = blockIdx.y * 256, n0 = blockIdx.x * 128;
    const int NT = (Ktot + 63) / 64;

    float acc[2][8][4];
    #pragma unroll
    for (int mt = 0; mt < 2; mt++)
        #pragma unroll
        for (int nt = 0; nt < 8; nt++)
            #pragma unroll
            for (int j = 0; j < 4; j++) acc[mt][nt][j] = 0.f;

    auto load_chunk = [&](int kt, int buf) {
        const int kc = kt * 64;
        const uint32_t bufbase = sb + buf * G2_BUF;
        #pragma unroll
        for (int it = 0; it < 4; it++) {
            int i = it * 512 + tid;
            int r = i >> 3, c16 = i & 7;
            cp_async16(bufbase + SWZ128(r * 128 + c16 * 16),
                       A + (size_t)(m0 + r) * Ktot + kc + c16 * 8, 16);
        }
        #pragma unroll
        for (int it = 0; it < 2; it++) {
            int i = it * 512 + tid;
            int r = i >> 3, c16 = i & 7;
            int gr = n0 + r;
            bool inb = gr < Ntot;
            cp_async16(bufbase + 32768 + SWZ128(r * 128 + c16 * 16),
                       B + (inb ? ((size_t)gr * Ktot + kc + c16 * 8) : 0), inb ? 16u : 0u);
        }
        CP_COMMIT();
    };

    load_chunk(0, 0);
    const int g8 = lane >> 3, rg = lane & 7;

    for (int kt = 0; kt < NT; kt++) {
        const int buf = kt & 1;
        if (kt + 1 < NT) { load_chunk(kt + 1, buf ^ 1); CP_WAIT(1); }
        else             { CP_WAIT(0); }
        __syncthreads();

        const uint32_t bA = sb + buf * G2_BUF;
        const uint32_t bB = bA + 32768;

        #pragma unroll
        for (int kk = 0; kk < 4; kk++) {
            const int kb = kk * 32;
            uint32_t a4[2][4], b[8][2];
            #pragma unroll
            for (int mt = 0; mt < 2; mt++) {
                int row = wm * 32 + mt * 16 + (g8 & 1) * 8 + rg;
                ldsm_x4(a4[mt], bA + SWZ128(row * 128 + kb + (g8 >> 1) * 16));
            }
            #pragma unroll
            for (int p = 0; p < 4; p++) {
                int rowb = wn * 64 + p * 16 + (g8 >> 1) * 8 + rg;
                uint32_t t[4];
                ldsm_x4(t, bB + SWZ128(rowb * 128 + kb + (g8 & 1) * 16));
                b[2 * p][0] = t[0]; b[2 * p][1] = t[1];
                b[2 * p + 1][0] = t[2]; b[2 * p + 1][1] = t[3];
            }
            #pragma unroll
            for (int mt = 0; mt < 2; mt++)
                #pragma unroll
                for (int nt = 0; nt < 8; nt++)
                    mma16816h(acc[mt][nt], a4[mt], b[nt]);
        }
        __syncthreads();
    }

    #pragma unroll
    for (int mt = 0; mt < 2; mt++) {
        int row = m0 + wm * 32 + mt * 16 + (lane >> 2);
        #pragma unroll
        for (int nt = 0; nt < 8; nt++) {
            int col = n0 + wn * 64 + nt * 8 + (lane & 3) * 2;
            if (col < Ntot) {
                float b0 = bias[col], b1 = bias[col + 1];
                float2 v0 = make_float2(acc[mt][nt][0] + b0, acc[mt][nt][1] + b1);
                float2 v1 = make_float2(acc[mt][nt][2] + b0, acc[mt][nt][3] + b1);
                *(float2*)&C[(size_t)row * Ntot + col] = v0;
                *(float2*)&C[(size_t)(row + 8) * Ntot + col] = v1;
            }
        }
    }
}

// =========================================================================
// persistent LSTM recurrence, fp16 single-W, 64 CTAs x 32 gate rows.
// CTA b owns gate rows n0 = b*32 (d in [b*8, b*8+8)); 256 threads (8 warps).
// smem: W0 64K | W1 64K | A 3x16K | gates 128x33 f32 ~16.5K
// =========================================================================
#define PSM_W0 0
#define PSM_W1 65536
#define PSM_A  131072
#define PSM_G  180224
#define GSTRIDE 33
#define PERS_SMEM (180224 + 128 * GSTRIDE * 4)

__global__ __launch_bounds__(256) void lstm_persistent_kernel(
    const __half* __restrict__ Wc0, const __half* __restrict__ Wc1,
    __half* __restrict__ h0fA, __half* __restrict__ h0fB,
    const __half* __restrict__ h1zf, __half* __restrict__ H1f,
    const float* __restrict__ bias0, const float* __restrict__ bias0f,
    const float* __restrict__ bias1)
{
    extern __shared__ char smem[];
    const uint32_t sb = smem_u32(smem);
    float* gates = (float*)(smem + PSM_G);
    const int tid = threadIdx.x, wid = tid >> 5, lane = tid & 31;
    const int n0 = blockIdx.x * 32;
    const int g8 = lane >> 3, rg = lane & 7;

    // persistent weight slices: per layer 16 chunks x (32 rows x 128B) = 64KB
    #pragma unroll
    for (int L = 0; L < 2; L++) {
        const __half* src = L ? Wc1 : Wc0;
        const uint32_t dstb = L ? PSM_W1 : PSM_W0;
        #pragma unroll
        for (int it = 0; it < 16; it++) {
            int i = it * 256 + tid;
            int ch = i >> 8, r = (i >> 3) & 31, c16 = i & 7;
            cp_async16(sb + dstb + ch * 4096 + SWZ128(r * 128 + c16 * 16),
                       src + (size_t)(n0 + r) * 1024 + ch * 64 + c16 * 8, 16);
        }
    }
    CP_COMMIT();

    float rb0[4][4], rb0f[4][4], rb1[4][4];
    #pragma unroll
    for (int it = 0; it < 4; it++) {
        int idx = it * 256 + tid;
        int dd = idx & 7;
        int d = blockIdx.x * 8 + dd;
        #pragma unroll
        for (int g = 0; g < 4; g++) {
            rb0[it][g]  = bias0[g * 512 + d];
            rb0f[it][g] = bias0f[g * 512 + d];
            rb1[it][g]  = bias1[g * 512 + d];
        }
    }

    float c0r[4] = {0.f, 0.f, 0.f, 0.f}, c1r[4] = {0.f, 0.f, 0.f, 0.f};
    unsigned epoch = 0;
    int cur = 0;

    for (int t = 0; t < TT; t++) {
        #pragma unroll
        for (int layer = 0; layer < 2; layer++) {
            const __half *xf, *hf;
            int kstart;
            if (layer == 0) {
                kstart = (t == 0) ? 8 : 0;
                xf = (t == 0) ? (const __half*)0 : H1f + (size_t)(t - 1) * BB * DD;
                hf = cur ? h0fB : h0fA;
            } else {
                kstart = 0;
                xf = cur ? h0fA : h0fB;
                hf = (t == 0) ? h1zf : H1f + (size_t)(t - 1) * BB * DD;
            }
            const uint32_t wbase = sb + (layer ? PSM_W1 : PSM_W0);

            auto load_chunk = [&](int ch, int buf) {
                const __half* src = (ch < 8) ? xf : hf;
                int koff = (ch & 7) * 64;
                const uint32_t base = sb + PSM_A + buf * 16384;
                #pragma unroll
                for (int it = 0; it < 4; it++) {
                    int i = it * 256 + tid;
                    int r = i >> 3, c16 = i & 7;
                    cp_async16(base + SWZ128(r * 128 + c16 * 16),
                               src + (size_t)r * 512 + koff + c16 * 8, 16);
                }
                CP_COMMIT();
            };

            float acc[4][4];
            #pragma unroll
            for (int b = 0; b < 4; b++)
                #pragma unroll
                for (int j = 0; j < 4; j++) acc[b][j] = 0.f;

            load_chunk(kstart, 0);
            if (kstart + 1 < 16) load_chunk(kstart + 1, 1);
            for (int ch = kstart; ch < 16; ch++) {
                const int i = ch - kstart;
                if (ch + 1 < 16) { CP_WAIT(1); }
                else             { CP_WAIT(0); }
                __syncthreads();
                if (ch + 2 < 16) load_chunk(ch + 2, (i + 2) % 3);

                const uint32_t bA = sb + PSM_A + (i % 3) * 16384;
                const uint32_t bW = wbase + ch * 4096;

                #pragma unroll
                for (int kk = 0; kk < 4; kk++) {
                    const int kb = kk * 32;
                    uint32_t a4[4], t[4], t2[4];
                    int row = wid * 16 + (g8 & 1) * 8 + rg;
                    ldsm_x4(a4, bA + SWZ128(row * 128 + kb + (g8 >> 1) * 16));
                    int rowb = (g8 >> 1) * 8 + rg;
                    uint32_t offc = kb + (g8 & 1) * 16;
                    ldsm_x4(t,  bW + SWZ128(rowb * 128 + offc));
                    ldsm_x4(t2, bW + SWZ128((rowb + 16) * 128 + offc));
                    uint32_t b0[2] = {t[0], t[1]},  b1[2] = {t[2], t[3]};
                    uint32_t b2[2] = {t2[0], t2[1]}, b3[2] = {t2[2], t2[3]};
                    mma16816h(acc[0], a4, b0);
                    mma16816h(acc[1], a4, b1);
                    mma16816h(acc[2], a4, b2);
                    mma16816h(acc[3], a4, b3);
                }
            }
            __syncthreads();

            // stage gates (128 rows x 32 cols, stride 33 vs bank conflicts)
            {
                int r0 = wid * 16 + (lane >> 2);
                int cb = (lane & 3) * 2;
                #pragma unroll
                for (int b = 0; b < 4; b++) {
                    gates[r0 * GSTRIDE + b * 8 + cb]           = acc[b][0];
                    gates[r0 * GSTRIDE + b * 8 + cb + 1]       = acc[b][1];
                    gates[(r0 + 8) * GSTRIDE + b * 8 + cb]     = acc[b][2];
                    gates[(r0 + 8) * GSTRIDE + b * 8 + cb + 1] = acc[b][3];
                }
            }
            __syncthreads();

            __half* of = (layer == 0) ? (cur ? h0fA : h0fB) : (H1f + (size_t)t * BB * DD);
            #pragma unroll
            for (int it = 0; it < 4; it++) {
                int idx = it * 256 + tid;
                int row = idx >> 3, dd = idx & 7;
                int d = blockIdx.x * 8 + dd;
                const float* rb = (layer == 0) ? ((t == 0) ? rb0[it] : rb0f[it]) : rb1[it];
                float gi = gates[row * GSTRIDE + dd * 4 + 0] + rb[0];
                float gf = gates[row * GSTRIDE + dd * 4 + 1] + rb[1];
                float gg = gates[row * GSTRIDE + dd * 4 + 2] + rb[2];
                float go = gates[row * GSTRIDE + dd * 4 + 3] + rb[3];
                float i_ = 1.f / (1.f + expf(-gi));
                float f_ = 1.f / (1.f + expf(-gf));
                float g_ = tanhf(gg);
                float o_ = 1.f / (1.f + expf(-go));
                float* cr = (layer == 0) ? &c0r[it] : &c1r[it];
                float cn = f_ * (*cr) + i_ * g_;
                *cr = cn;
                of[row * 512 + d] = __float2half_rn(o_ * tanhf(cn));
            }

            __threadfence();
            __syncthreads();
            epoch++;
            if (tid == 0) {
                atomicAdd(&g_bar, 1u);
                unsigned target = epoch * NCTA;
                volatile unsigned* p = &g_bar;
                while (*p < target) { }
                __threadfence();
            }
            __syncthreads();
        }
        cur ^= 1;
    }
}

// =========================================================================
// host
// =========================================================================
extern "C" void kernel_launch(void* const* d_in, const int* in_sizes, int n_in,
                              void* d_out, int out_size) {
    const float* input_ = (const float*)d_in[0];
    const float* W_ih0  = (const float*)d_in[1];
    const float* W_hh0  = (const float*)d_in[2];
    const float* b_ih0  = (const float*)d_in[3];
    const float* b_hh0  = (const float*)d_in[4];
    const float* W_ih1  = (const float*)d_in[5];
    const float* W_hh1  = (const float*)d_in[6];
    const float* b_ih1  = (const float*)d_in[7];
    const float* b_hh1  = (const float*)d_in[8];
    const float* W_enc  = (const float*)d_in[9];
    const float* b_enc  = (const float*)d_in[10];
    float* out = (float*)d_out;

    float *p_Mtmp, *p_bias0, *p_bias0f, *p_bias1;
    __half *p_A1f, *p_B1f, *p_B2f;
    __half *p_H1f, *p_h0fA, *p_h0fB, *p_h1zf, *p_Wc0, *p_Wc1;
    cudaGetSymbolAddress((void**)&p_Mtmp,   g_Mtmp);
    cudaGetSymbolAddress((void**)&p_bias0,  g_bias0);
    cudaGetSymbolAddress((void**)&p_bias0f, g_bias0f);
    cudaGetSymbolAddress((void**)&p_bias1,  g_bias1);
    cudaGetSymbolAddress((void**)&p_A1f,    g_A1f);
    cudaGetSymbolAddress((void**)&p_B1f,    g_B1f);
    cudaGetSymbolAddress((void**)&p_B2f,    g_B2f);
    cudaGetSymbolAddress((void**)&p_H1f,    g_H1f);
    cudaGetSymbolAddress((void**)&p_h0fA,   g_h0fA);
    cudaGetSymbolAddress((void**)&p_h0fB,   g_h0fB);
    cudaGetSymbolAddress((void**)&p_h1zf,   g_h1zf);
    cudaGetSymbolAddress((void**)&p_Wc0,    g_Wc0);
    cudaGetSymbolAddress((void**)&p_Wc1,    g_Wc1);

    cudaFuncSetAttribute((const void*)gemm1_f16_kernel,
                         cudaFuncAttributeMaxDynamicSharedMemorySize, G1_SMEM);
    cudaFuncSetAttribute((const void*)gemm2_f16_kernel,
                         cudaFuncAttributeMaxDynamicSharedMemorySize, G2_SMEM);
    cudaFuncSetAttribute((const void*)lstm_persistent_kernel,
                         cudaFuncAttributeMaxDynamicSharedMemorySize, PERS_SMEM);

    // ---- prep ----
    prep_misc_kernel<<<(BB * DD + 255) / 256, 256>>>(input_, b_ih0, b_hh0, b_ih1, b_hh1);
    cudaMemsetAsync(p_Mtmp, 0, (size_t)GG * DD * sizeof(float));
    conv_a1_bias_kernel<<<GG, 256>>>(W_ih0, b_enc);   // A1f + bias0f in one pass

    dim3 tb(32, 8);
    transpose_f16_kernel<<<dim3(DD / 32, (VV + 31) / 32), tb>>>(W_enc, p_B1f);
    f32_to_f16_kernel<<<(VV * DD / 4 + 255) / 256, 256>>>(W_enc, p_B2f, VV * DD);

    // GEMM1: Mtmp += W_ih0 @ W_enc^T  [fp16 single, BM=256, split-K=4, 128 CTAs]
    gemm1_f16_kernel<<<dim3(DD / 128, GG / 256, 4), 512, G1_SMEM>>>(
        p_A1f, p_B1f, p_Mtmp);

    // fused, gate-interleaved fp16 cell weights (single term)
    build_cell_w_kernel<<<2048, 256>>>(p_Mtmp, W_hh0, p_Wc0);
    build_cell_w_kernel<<<2048, 256>>>(W_ih1, W_hh1, p_Wc1);

    // ---- recurrence: one persistent launch, 64 CTAs ----
    lstm_persistent_kernel<<<NCTA, 256, PERS_SMEM>>>(
        p_Wc0, p_Wc1, p_h0fA, p_h0fB, p_h1zf, p_H1f,
        p_bias0, p_bias0f, p_bias1);

    // GEMM2: OUT(2560,10000) = H1f @ B2f^T + b_enc  [fp16 single-B]
    gemm2_f16_kernel<<<dim3((VV + 127) / 128, (TT * BB) / 256), 512, G2_SMEM>>>(
        p_H1f, p_B2f, out, b_enc, TT * BB, VV, DD);
}

// round 15
// speedup vs baseline: 1.5535x; 1.1140x over previous
#include <cuda_runtime.h>
#include <cuda_fp16.h>
#include <math.h>
#include <stdint.h>

#define BB 128     // batch
#define DD 512     // hidden
#define GG 2048    // 4*D
#define VV 10000   // vocab
#define TT 20      // timesteps
#define NCTA 128   // persistent kernel CTAs (64 gate-slices x 2 batch halves)

// ---------------- device scratch (no allocation allowed) ----------------
__device__ float g_Mtmp[GG * DD];    // W_ih0 @ W_enc (fp32, split-K red target)
__device__ float g_bias0[GG];
__device__ float g_bias0f[GG];
__device__ float g_bias1[GG];
__device__ unsigned g_bar;
// fp16 operands for GEMM1 (all single-term)
__device__ __half g_A1f[(size_t)GG * VV];          // W_ih0 (2048,10000) fp16
__device__ __half g_B1f[(size_t)DD * VV];          // W_enc^T (512,10000) fp16
// fp16 operand for GEMM2
__device__ __half g_B2f[(size_t)VV * DD];          // W_enc (10000,512) fp16
// fp16 recurrence state
__device__ __half g_H1f[TT * BB * DD];
__device__ __half g_h0fA[BB * DD], g_h0fB[BB * DD];
__device__ __half g_h1zf[BB * DD];
// fused, gate-interleaved cell weights (fp16 single): rows n'=d*4+gate, K=1024=[x|h]
__device__ __half g_Wc0[(size_t)GG * 1024];
__device__ __half g_Wc1[(size_t)GG * 1024];

// =========================================================================
// helpers
// =========================================================================
__device__ __forceinline__ uint32_t smem_u32(const void* p) {
    uint32_t a;
    asm("{ .reg .u64 t; cvta.to.shared.u64 t, %1; cvt.u32.u64 %0, t; }" : "=r"(a) : "l"(p));
    return a;
}
#define SWZ128(o) ((o) ^ (((o) >> 3) & 0x70))

__device__ __forceinline__ void ldsm_x4(uint32_t* r, uint32_t addr) {
    asm volatile("ldmatrix.sync.aligned.m8n8.x4.shared.b16 {%0,%1,%2,%3}, [%4];"
                 : "=r"(r[0]), "=r"(r[1]), "=r"(r[2]), "=r"(r[3]) : "r"(addr));
}
__device__ __forceinline__ void mma16816h(float* d, const uint32_t* a, const uint32_t* b) {
    asm volatile(
        "mma.sync.aligned.m16n8k16.row.col.f32.f16.f16.f32 "
        "{%0,%1,%2,%3}, {%4,%5,%6,%7}, {%8,%9}, {%0,%1,%2,%3};"
        : "+f"(d[0]), "+f"(d[1]), "+f"(d[2]), "+f"(d[3])
        : "r"(a[0]), "r"(a[1]), "r"(a[2]), "r"(a[3]), "r"(b[0]), "r"(b[1]));
}
__device__ __forceinline__ void cp_async16(uint32_t daddr, const void* g, unsigned sz) {
    asm volatile("cp.async.cg.shared.global [%0], [%1], 16, %2;"
                 :: "r"(daddr), "l"(g), "r"(sz));
}
__device__ __forceinline__ void red_addf(float* p, float v) {
    asm volatile("red.global.add.f32 [%0], %1;" :: "l"(p), "f"(v) : "memory");
}
#define CP_COMMIT() asm volatile("cp.async.commit_group;" ::: "memory")
#define CP_WAIT(n)  asm volatile("cp.async.wait_group %0;" :: "n"(n) : "memory")

// =========================================================================
// prep kernels
// =========================================================================
__global__ void prep_misc_kernel(const float* __restrict__ input_,
                                 const float* __restrict__ b_ih0, const float* __restrict__ b_hh0,
                                 const float* __restrict__ b_ih1, const float* __restrict__ b_hh1) {
    int i = blockIdx.x * blockDim.x + threadIdx.x;
    if (i == 0) g_bar = 0u;
    if (i < GG) {
        g_bias0[i] = b_ih0[i] + b_hh0[i];
        g_bias1[i] = b_ih1[i] + b_hh1[i];
    }
    if (i < BB * DD) g_h1zf[i] = __float2half_rn(0.f);
    if (i < BB * DD / 4) {
        float4 v = *(const float4*)(input_ + i * 4);
        __half h[4] = {__float2half_rn(v.x), __float2half_rn(v.y),
                       __float2half_rn(v.z), __float2half_rn(v.w)};
        *(uint2*)(g_h0fA + i * 4) = *(uint2*)h;
    }
}

// fused: A1f = fp16(W_ih0)  AND  bias0f[g] = bias0[g] + W_ih0[g,:]·b_enc
__global__ void conv_a1_bias_kernel(const float* __restrict__ W_ih0,
                                    const float* __restrict__ b_enc) {
    __shared__ float red[256];
    int g = blockIdx.x;
    const float* src = W_ih0 + (size_t)g * VV;
    __half* dst = g_A1f + (size_t)g * VV;
    float s = 0.f;
    for (int v4 = threadIdx.x * 4; v4 < VV; v4 += 1024) {
        float4 v = *(const float4*)(src + v4);
        __half h[4] = {__float2half_rn(v.x), __float2half_rn(v.y),
                       __float2half_rn(v.z), __float2half_rn(v.w)};
        *(uint2*)(dst + v4) = *(uint2*)h;
        float4 b = *(const float4*)(b_enc + v4);
        s += v.x * b.x + v.y * b.y + v.z * b.z + v.w * b.w;
    }
    red[threadIdx.x] = s;
    __syncthreads();
    for (int o = 128; o > 0; o >>= 1) {
        if (threadIdx.x < o) red[threadIdx.x] += red[threadIdx.x + o];
        __syncthreads();
    }
    if (threadIdx.x == 0) g_bias0f[g] = g_bias0[g] + red[0];
}

// W_enc (10000,512) fp32 -> B1f (512,10000) fp16 (fused transpose + convert)
__global__ void transpose_f16_kernel(const float* __restrict__ src, __half* __restrict__ dst) {
    __shared__ float tile[32][33];
    int c0 = blockIdx.x * 32;
    int r0 = blockIdx.y * 32;
    int c = c0 + threadIdx.x;
    for (int i = threadIdx.y; i < 32; i += 8) {
        int r = r0 + i;
        if (r < VV) tile[i][threadIdx.x] = src[(size_t)r * DD + c];
    }
    __syncthreads();
    int r = r0 + threadIdx.x;
    if (r < VV) {
        for (int i = threadIdx.y; i < 32; i += 8)
            dst[(size_t)(c0 + i) * VV + r] = __float2half_rn(tile[threadIdx.x][i]);
    }
}

// fp32 -> fp16 single
__global__ void f32_to_f16_kernel(const float* __restrict__ src, __half* __restrict__ dst, int n) {
    int i = (blockIdx.x * blockDim.x + threadIdx.x) * 4;
    if (i < n) {
        float4 v = *(const float4*)(src + i);
        __half h[4] = {__float2half_rn(v.x), __float2half_rn(v.y),
                       __float2half_rn(v.z), __float2half_rn(v.w)};
        *(uint2*)(dst + i) = *(uint2*)h;
    }
}

// fused cell weights (fp16 single): out (2048,1024): n'=d*4+gate, src n=gate*512+d
__global__ void build_cell_w_kernel(const float* __restrict__ srcX, const float* __restrict__ srcH,
                                    __half* __restrict__ w) {
    int idx = blockIdx.x * 256 + threadIdx.x;
    int e = idx * 4;
    int np = e >> 10, k4 = e & 1023;
    int d = np >> 2, gate = np & 3;
    int n = gate * 512 + d;
    const float* s = (k4 < 512) ? (srcX + (size_t)n * 512 + k4)
                                : (srcH + (size_t)n * 512 + (k4 - 512));
    float4 v = *(const float4*)s;
    __half h[4] = {__float2half_rn(v.x), __float2half_rn(v.y),
                   __float2half_rn(v.z), __float2half_rn(v.w)};
    *(uint2*)(w + (size_t)np * 1024 + k4) = *(uint2*)h;
}

// =========================================================================
// GEMM1 (fp16 single, split-K=4): Mtmp(2048,512) += A(2048,10000)f16 @ B(512,10000)^T
// BM=256 (512 thr), BN=128, BK=64. grid (4, 8, 4) = 128 CTAs. KSPLIT=2560.
// =========================================================================
#define G1_BUF 49152
#define G1_SMEM (2 * G1_BUF)
#define KSPLIT 2560

__global__ __launch_bounds__(512) void gemm1_f16_kernel(
    const __half* __restrict__ A, const __half* __restrict__ B,
    float* __restrict__ C)
{
    extern __shared__ char smem[];
    const uint32_t sb = smem_u32(smem);
    const int tid = threadIdx.x, wid = tid >> 5, lane = tid & 31;
    const int wm = wid & 7, wn = wid >> 3;
    const int m0 = blockIdx.y * 256, n0 = blockIdx.x * 128;
    const int kb0 = blockIdx.z * KSPLIT;
    const int kend = min(kb0 + KSPLIT, VV);
    const int NT = (kend - kb0 + 63) / 64;

    float acc[2][8][4];
    #pragma unroll
    for (int mt = 0; mt < 2; mt++)
        #pragma unroll
        for (int nt = 0; nt < 8; nt++)
            #pragma unroll
            for (int j = 0; j < 4; j++) acc[mt][nt][j] = 0.f;

    auto load_chunk = [&](int kt, int buf) {
        const int kc = kb0 + kt * 64;
        const uint32_t bufbase = sb + buf * G1_BUF;
        #pragma unroll
        for (int it = 0; it < 4; it++) {
            int i = it * 512 + tid;
            int r = i >> 3, c16 = i & 7;
            int gk = kc + c16 * 8;
            bool inb = gk < kend;
            cp_async16(bufbase + SWZ128(r * 128 + c16 * 16),
                       A + (inb ? ((size_t)(m0 + r) * VV + gk) : 0), inb ? 16u : 0u);
        }
        #pragma unroll
        for (int it = 0; it < 2; it++) {
            int i = it * 512 + tid;
            int r = i >> 3, c16 = i & 7;
            int gk = kc + c16 * 8;
            bool inb = gk < kend;
            cp_async16(bufbase + 32768 + SWZ128(r * 128 + c16 * 16),
                       B + (inb ? ((size_t)(n0 + r) * VV + gk) : 0), inb ? 16u : 0u);
        }
        CP_COMMIT();
    };

    load_chunk(0, 0);
    const int g8 = lane >> 3, rg = lane & 7;

    for (int kt = 0; kt < NT; kt++) {
        const int buf = kt & 1;
        if (kt + 1 < NT) { load_chunk(kt + 1, buf ^ 1); CP_WAIT(1); }
        else             { CP_WAIT(0); }
        __syncthreads();

        const uint32_t bA = sb + buf * G1_BUF;
        const uint32_t bB = bA + 32768;

        #pragma unroll
        for (int kk = 0; kk < 4; kk++) {
            const int kb = kk * 32;
            uint32_t a4[2][4], b[8][2];
            #pragma unroll
            for (int mt = 0; mt < 2; mt++) {
                int row = wm * 32 + mt * 16 + (g8 & 1) * 8 + rg;
                ldsm_x4(a4[mt], bA + SWZ128(row * 128 + kb + (g8 >> 1) * 16));
            }
            #pragma unroll
            for (int p = 0; p < 4; p++) {
                int rowb = wn * 64 + p * 16 + (g8 >> 1) * 8 + rg;
                uint32_t t[4];
                ldsm_x4(t, bB + SWZ128(rowb * 128 + kb + (g8 & 1) * 16));
                b[2 * p][0] = t[0]; b[2 * p][1] = t[1];
                b[2 * p + 1][0] = t[2]; b[2 * p + 1][1] = t[3];
            }
            #pragma unroll
            for (int mt = 0; mt < 2; mt++)
                #pragma unroll
                for (int nt = 0; nt < 8; nt++)
                    mma16816h(acc[mt][nt], a4[mt], b[nt]);
        }
        __syncthreads();
    }

    #pragma unroll
    for (int mt = 0; mt < 2; mt++) {
        int row = m0 + wm * 32 + mt * 16 + (lane >> 2);
        #pragma unroll
        for (int nt = 0; nt < 8; nt++) {
            int col = n0 + wn * 64 + nt * 8 + (lane & 3) * 2;
            float* p0 = &C[(size_t)row * DD + col];
            float* p1 = &C[(size_t)(row + 8) * DD + col];
            red_addf(p0, acc[mt][nt][0]);
            red_addf(p0 + 1, acc[mt][nt][1]);
            red_addf(p1, acc[mt][nt][2]);
            red_addf(p1 + 1, acc[mt][nt][3]);
        }
    }
}

// =========================================================================
// GEMM2 (fp16 single-B): OUT(M,N) = A(M,K)f16 @ B(N,K)^T + bias.
// BM=256, BN=128, BK=64; 512 threads.
// =========================================================================
#define G2_BUF 49152
#define G2_SMEM (2 * G2_BUF)

__global__ __launch_bounds__(512) void gemm2_f16_kernel(
    const __half* __restrict__ A, const __half* __restrict__ B,
    float* __restrict__ C, const float* __restrict__ bias,
    int Mtot, int Ntot, int Ktot)
{
    extern __shared__ char smem[];
    const uint32_t sb = smem_u32(smem);
    const int tid = threadIdx.x, wid = tid >> 5, lane = tid & 31;
    const int wm = wid & 7, wn = wid >> 3;
    const int m0 = blockIdx.y * 256, n0 = blockIdx.x * 128;
    const int NT = (Ktot + 63) / 64;

    float acc[2][8][4];
    #pragma unroll
    for (int mt = 0; mt < 2; mt++)
        #pragma unroll
        for (int nt = 0; nt < 8; nt++)
            #pragma unroll
            for (int j = 0; j < 4; j++) acc[mt][nt][j] = 0.f;

    auto load_chunk = [&](int kt, int buf) {
        const int kc = kt * 64;
        const uint32_t bufbase = sb + buf * G2_BUF;
        #pragma unroll
        for (int it = 0; it < 4; it++) {
            int i = it * 512 + tid;
            int r = i >> 3, c16 = i & 7;
            cp_async16(bufbase + SWZ128(r * 128 + c16 * 16),
                       A + (size_t)(m0 + r) * Ktot + kc + c16 * 8, 16);
        }
        #pragma unroll
        for (int it = 0; it < 2; it++) {
            int i = it * 512 + tid;
            int r = i >> 3, c16 = i & 7;
            int gr = n0 + r;
            bool inb = gr < Ntot;
            cp_async16(bufbase + 32768 + SWZ128(r * 128 + c16 * 16),
                       B + (inb ? ((size_t)gr * Ktot + kc + c16 * 8) : 0), inb ? 16u : 0u);
        }
        CP_COMMIT();
    };

    load_chunk(0, 0);
    const int g8 = lane >> 3, rg = lane & 7;

    for (int kt = 0; kt < NT; kt++) {
        const int buf = kt & 1;
        if (kt + 1 < NT) { load_chunk(kt + 1, buf ^ 1); CP_WAIT(1); }
        else             { CP_WAIT(0); }
        __syncthreads();

        const uint32_t bA = sb + buf * G2_BUF;
        const uint32_t bB = bA + 32768;

        #pragma unroll
        for (int kk = 0; kk < 4; kk++) {
            const int kb = kk * 32;
            uint32_t a4[2][4], b[8][2];
            #pragma unroll
            for (int mt = 0; mt < 2; mt++) {
                int row = wm * 32 + mt * 16 + (g8 & 1) * 8 + rg;
                ldsm_x4(a4[mt], bA + SWZ128(row * 128 + kb + (g8 >> 1) * 16));
            }
            #pragma unroll
            for (int p = 0; p < 4; p++) {
                int rowb = wn * 64 + p * 16 + (g8 >> 1) * 8 + rg;
                uint32_t t[4];
                ldsm_x4(t, bB + SWZ128(rowb * 128 + kb + (g8 & 1) * 16));
                b[2 * p][0] = t[0]; b[2 * p][1] = t[1];
                b[2 * p + 1][0] = t[2]; b[2 * p + 1][1] = t[3];
            }
            #pragma unroll
            for (int mt = 0; mt < 2; mt++)
                #pragma unroll
                for (int nt = 0; nt < 8; nt++)
                    mma16816h(acc[mt][nt], a4[mt], b[nt]);
        }
        __syncthreads();
    }

    #pragma unroll
    for (int mt = 0; mt < 2; mt++) {
        int row = m0 + wm * 32 + mt * 16 + (lane >> 2);
        #pragma unroll
        for (int nt = 0; nt < 8; nt++) {
            int col = n0 + wn * 64 + nt * 8 + (lane & 3) * 2;
            if (col < Ntot) {
                float b0 = bias[col], b1 = bias[col + 1];
                float2 v0 = make_float2(acc[mt][nt][0] + b0, acc[mt][nt][1] + b1);
                float2 v1 = make_float2(acc[mt][nt][2] + b0, acc[mt][nt][3] + b1);
                *(float2*)&C[(size_t)row * Ntot + col] = v0;
                *(float2*)&C[(size_t)(row + 8) * Ntot + col] = v1;
            }
        }
    }
}

// =========================================================================
// persistent LSTM recurrence: 128 CTAs = 64 gate-slices x 2 batch-halves.
// CTA: 64 batch rows x 32 gate rows. 256 threads (4m x 2n warps).
// K-chunks processed h-part (8..15) first, then x-part (0..7); the grid-
// barrier WAIT is deferred until just before loading the first x chunk,
// hiding barrier latency behind stale-safe compute. Arrive posted at end.
// smem: W0 64K | W1 64K | A 3x8K | gates 64x33 f32
// =========================================================================
#define PSM_W0 0
#define PSM_W1 65536
#define PSM_A  131072
#define PSM_G  155648
#define GSTRIDE 33
#define PERS_SMEM (155648 + 64 * GSTRIDE * 4)

__global__ __launch_bounds__(256) void lstm_persistent_kernel(
    const __half* __restrict__ Wc0, const __half* __restrict__ Wc1,
    __half* __restrict__ h0fA, __half* __restrict__ h0fB,
    const __half* __restrict__ h1zf, __half* __restrict__ H1f,
    const float* __restrict__ bias0, const float* __restrict__ bias0f,
    const float* __restrict__ bias1)
{
    extern __shared__ char smem[];
    const uint32_t sb = smem_u32(smem);
    float* gates = (float*)(smem + PSM_G);
    const int tid = threadIdx.x, wid = tid >> 5, lane = tid & 31;
    const int gs = blockIdx.x >> 1;       // gate slice 0..63
    const int bh = blockIdx.x & 1;        // batch half
    const int n0 = gs * 32;
    const int b0 = bh * 64;
    const int wm = wid & 3, wn = wid >> 2;
    const int g8 = lane >> 3, rg = lane & 7;

    // persistent weight slices: per layer 16 chunks x (32 rows x 128B) = 64KB
    #pragma unroll
    for (int L = 0; L < 2; L++) {
        const __half* src = L ? Wc1 : Wc0;
        const uint32_t dstb = L ? PSM_W1 : PSM_W0;
        #pragma unroll
        for (int it = 0; it < 16; it++) {
            int i = it * 256 + tid;
            int ch = i >> 8, r = (i >> 3) & 31, c16 = i & 7;
            cp_async16(sb + dstb + ch * 4096 + SWZ128(r * 128 + c16 * 16),
                       src + (size_t)(n0 + r) * 1024 + ch * 64 + c16 * 8, 16);
        }
    }
    CP_COMMIT();

    // hoisted bias regs: thread owns (row = idx>>3 local, dd = idx&7), it<2
    float rb0[2][4], rb0f[2][4], rb1[2][4];
    #pragma unroll
    for (int it = 0; it < 2; it++) {
        int idx = it * 256 + tid;
        int dd = idx & 7;
        int d = gs * 8 + dd;
        #pragma unroll
        for (int g = 0; g < 4; g++) {
            rb0[it][g]  = bias0[g * 512 + d];
            rb0f[it][g] = bias0f[g * 512 + d];
            rb1[it][g]  = bias1[g * 512 + d];
        }
    }

    float c0r[2] = {0.f, 0.f}, c1r[2] = {0.f, 0.f};
    unsigned epoch = 0;
    int cur = 0;

    for (int t = 0; t < TT; t++) {
        #pragma unroll
        for (int layer = 0; layer < 2; layer++) {
            const __half *xf, *hf;
            int kstart;
            if (layer == 0) {
                kstart = (t == 0) ? 8 : 0;
                xf = (t == 0) ? (const __half*)0 : H1f + (size_t)(t - 1) * BB * DD;
                hf = cur ? h0fB : h0fA;
            } else {
                kstart = 0;
                xf = cur ? h0fA : h0fB;     // fresh h0 from layer 0 (this t)
                hf = (t == 0) ? h1zf : H1f + (size_t)(t - 1) * BB * DD;
            }
            const uint32_t wbase = sb + (layer ? PSM_W1 : PSM_W0);
            const int NJ = 16 - kstart;
            // order: h chunks (8..15) first, then x chunks (0..7)
            auto chunk_of = [&](int j) { return (8 + j) & 15; };

            auto load_chunk = [&](int ch, int buf) {
                const __half* src = (ch < 8) ? xf : hf;
                int koff = (ch & 7) * 64;
                const uint32_t base = sb + PSM_A + buf * 8192;
                #pragma unroll
                for (int it = 0; it < 2; it++) {
                    int i = it * 256 + tid;
                    int r = i >> 3, c16 = i & 7;
                    cp_async16(base + SWZ128(r * 128 + c16 * 16),
                               src + (size_t)(b0 + r) * 512 + koff + c16 * 8, 16);
                }
                CP_COMMIT();
            };

            float acc[2][4];
            #pragma unroll
            for (int b = 0; b < 2; b++)
                #pragma unroll
                for (int j = 0; j < 4; j++) acc[b][j] = 0.f;

            load_chunk(chunk_of(0), 0);
            if (NJ > 1) load_chunk(chunk_of(1), 1);

            for (int j = 0; j < NJ; j++) {
                if (j + 1 < NJ) { CP_WAIT(1); }
                else            { CP_WAIT(0); }
                __syncthreads();
                if (j + 2 < NJ) {
                    // deferred grid-barrier wait before FIRST x-chunk load
                    if (chunk_of(j + 2) < 8 && chunk_of(j + 1) >= 8) {
                        if (tid == 0) {
                            unsigned target = epoch * NCTA;
                            volatile unsigned* p = &g_bar;
                            while (*p < target) { }
                            __threadfence();
                        }
                        __syncthreads();
                    }
                    load_chunk(chunk_of(j + 2), (j + 2) % 3);
                }

                const int ch = chunk_of(j);
                const uint32_t bA = sb + PSM_A + (j % 3) * 8192;
                const uint32_t bW = wbase + ch * 4096;

                #pragma unroll
                for (int kk = 0; kk < 4; kk++) {
                    const int kb = kk * 32;
                    uint32_t a4[4], tw[4];
                    int row = wm * 16 + (g8 & 1) * 8 + rg;
                    ldsm_x4(a4, bA + SWZ128(row * 128 + kb + (g8 >> 1) * 16));
                    int rowb = wn * 16 + (g8 >> 1) * 8 + rg;
                    ldsm_x4(tw, bW + SWZ128(rowb * 128 + kb + (g8 & 1) * 16));
                    uint32_t b0f[2] = {tw[0], tw[1]}, b1f[2] = {tw[2], tw[3]};
                    mma16816h(acc[0], a4, b0f);
                    mma16816h(acc[1], a4, b1f);
                }
            }
            __syncthreads();

            // stage gates (64 rows x 32 cols, stride 33)
            {
                int r0 = wm * 16 + (lane >> 2);
                int cb = wn * 16 + (lane & 3) * 2;
                #pragma unroll
                for (int b = 0; b < 2; b++) {
                    gates[r0 * GSTRIDE + cb + b * 8]           = acc[b][0];
                    gates[r0 * GSTRIDE + cb + b * 8 + 1]       = acc[b][1];
                    gates[(r0 + 8) * GSTRIDE + cb + b * 8]     = acc[b][2];
                    gates[(r0 + 8) * GSTRIDE + cb + b * 8 + 1] = acc[b][3];
                }
            }
            __syncthreads();

            __half* of = (layer == 0) ? (cur ? h0fA : h0fB) : (H1f + (size_t)t * BB * DD);
            #pragma unroll
            for (int it = 0; it < 2; it++) {
                int idx = it * 256 + tid;
                int row = idx >> 3, dd = idx & 7;
                int d = gs * 8 + dd;
                const float* rb = (layer == 0) ? ((t == 0) ? rb0[it] : rb0f[it]) : rb1[it];
                float gi = gates[row * GSTRIDE + dd * 4 + 0] + rb[0];
                float gf = gates[row * GSTRIDE + dd * 4 + 1] + rb[1];
                float gg = gates[row * GSTRIDE + dd * 4 + 2] + rb[2];
                float go = gates[row * GSTRIDE + dd * 4 + 3] + rb[3];
                float i_ = 1.f / (1.f + expf(-gi));
                float f_ = 1.f / (1.f + expf(-gf));
                float g_ = tanhf(gg);
                float o_ = 1.f / (1.f + expf(-go));
                float* cr = (layer == 0) ? &c0r[it] : &c1r[it];
                float cn = f_ * (*cr) + i_ * g_;
                *cr = cn;
                of[(size_t)(b0 + row) * 512 + d] = __float2half_rn(o_ * tanhf(cn));
            }

            // arrive (no wait here — wait is deferred into next phase)
            __threadfence();
            __syncthreads();
            if (tid == 0) atomicAdd(&g_bar, 1u);
            epoch++;
        }
        cur ^= 1;
    }
}

// =========================================================================
// host
// =========================================================================
extern "C" void kernel_launch(void* const* d_in, const int* in_sizes, int n_in,
                              void* d_out, int out_size) {
    const float* input_ = (const float*)d_in[0];
    const float* W_ih0  = (const float*)d_in[1];
    const float* W_hh0  = (const float*)d_in[2];
    const float* b_ih0  = (const float*)d_in[3];
    const float* b_hh0  = (const float*)d_in[4];
    const float* W_ih1  = (const float*)d_in[5];
    const float* W_hh1  = (const float*)d_in[6];
    const float* b_ih1  = (const float*)d_in[7];
    const float* b_hh1  = (const float*)d_in[8];
    const float* W_enc  = (const float*)d_in[9];
    const float* b_enc  = (const float*)d_in[10];
    float* out = (float*)d_out;

    float *p_Mtmp, *p_bias0, *p_bias0f, *p_bias1;
    __half *p_A1f, *p_B1f, *p_B2f;
    __half *p_H1f, *p_h0fA, *p_h0fB, *p_h1zf, *p_Wc0, *p_Wc1;
    cudaGetSymbolAddress((void**)&p_Mtmp,   g_Mtmp);
    cudaGetSymbolAddress((void**)&p_bias0,  g_bias0);
    cudaGetSymbolAddress((void**)&p_bias0f, g_bias0f);
    cudaGetSymbolAddress((void**)&p_bias1,  g_bias1);
    cudaGetSymbolAddress((void**)&p_A1f,    g_A1f);
    cudaGetSymbolAddress((void**)&p_B1f,    g_B1f);
    cudaGetSymbolAddress((void**)&p_B2f,    g_B2f);
    cudaGetSymbolAddress((void**)&p_H1f,    g_H1f);
    cudaGetSymbolAddress((void**)&p_h0fA,   g_h0fA);
    cudaGetSymbolAddress((void**)&p_h0fB,   g_h0fB);
    cudaGetSymbolAddress((void**)&p_h1zf,   g_h1zf);
    cudaGetSymbolAddress((void**)&p_Wc0,    g_Wc0);
    cudaGetSymbolAddress((void**)&p_Wc1,    g_Wc1);

    cudaFuncSetAttribute((const void*)gemm1_f16_kernel,
                         cudaFuncAttributeMaxDynamicSharedMemorySize, G1_SMEM);
    cudaFuncSetAttribute((const void*)gemm2_f16_kernel,
                         cudaFuncAttributeMaxDynamicSharedMemorySize, G2_SMEM);
    cudaFuncSetAttribute((const void*)lstm_persistent_kernel,
                         cudaFuncAttributeMaxDynamicSharedMemorySize, PERS_SMEM);

    // ---- prep ----
    prep_misc_kernel<<<(BB * DD + 255) / 256, 256>>>(input_, b_ih0, b_hh0, b_ih1, b_hh1);
    cudaMemsetAsync(p_Mtmp, 0, (size_t)GG * DD * sizeof(float));
    conv_a1_bias_kernel<<<GG, 256>>>(W_ih0, b_enc);   // A1f + bias0f in one pass

    dim3 tb(32, 8);
    transpose_f16_kernel<<<dim3(DD / 32, (VV + 31) / 32), tb>>>(W_enc, p_B1f);
    f32_to_f16_kernel<<<(VV * DD / 4 + 255) / 256, 256>>>(W_enc, p_B2f, VV * DD);

    // GEMM1: Mtmp += W_ih0 @ W_enc^T  [fp16 single, BM=256, split-K=4, 128 CTAs]
    gemm1_f16_kernel<<<dim3(DD / 128, GG / 256, 4), 512, G1_SMEM>>>(
        p_A1f, p_B1f, p_Mtmp);

    // fused, gate-interleaved fp16 cell weights (single term)
    build_cell_w_kernel<<<2048, 256>>>(p_Mtmp, W_hh0, p_Wc0);
    build_cell_w_kernel<<<2048, 256>>>(W_ih1, W_hh1, p_Wc1);

    // ---- recurrence: one persistent launch, 128 CTAs (batch-split) ----
    lstm_persistent_kernel<<<NCTA, 256, PERS_SMEM>>>(
        p_Wc0, p_Wc1, p_h0fA, p_h0fB, p_h1zf, p_H1f,
        p_bias0, p_bias0f, p_bias1);

    // GEMM2: OUT(2560,10000) = H1f @ B2f^T + b_enc  [fp16 single-B]
    gemm2_f16_kernel<<<dim3((VV + 127) / 128, (TT * BB) / 256), 512, G2_SMEM>>>(
        p_H1f, p_B2f, out, b_enc, TT * BB, VV, DD);
}

// round 16
// speedup vs baseline: 1.6998x; 1.0941x over previous
#include <cuda_runtime.h>
#include <cuda_fp16.h>
#include <math.h>
#include <stdint.h>

#define BB 128     // batch
#define DD 512     // hidden
#define GG 2048    // 4*D
#define VV 10000   // vocab
#define TT 20      // timesteps
#define NCTA 128   // persistent kernel CTAs (64 gate-slices x 2 batch halves)

// ---------------- device scratch (no allocation allowed) ----------------
__device__ float g_Mtmp[GG * DD];    // W_ih0 @ W_enc (fp32, split-K red target)
__device__ float g_bias0[GG];
__device__ float g_bias0f[GG];
__device__ float g_bias1[GG];
__device__ unsigned g_bar;
// fp16 operands for GEMM1 (all single-term)
__device__ __half g_A1f[(size_t)GG * VV];          // W_ih0 (2048,10000) fp16
__device__ __half g_B1f[(size_t)DD * VV];          // W_enc^T (512,10000) fp16
// fp16 operand for GEMM2
__device__ __half g_B2f[(size_t)VV * DD];          // W_enc (10000,512) fp16
// fp16 recurrence state
__device__ __half g_H1f[TT * BB * DD];
__device__ __half g_h0fA[BB * DD], g_h0fB[BB * DD];
__device__ __half g_h1zf[BB * DD];
// fused, gate-interleaved cell weights (fp16 single): rows n'=d*4+gate, K=1024=[x|h]
__device__ __half g_Wc0[(size_t)GG * 1024];
__device__ __half g_Wc1[(size_t)GG * 1024];

// =========================================================================
// helpers
// =========================================================================
__device__ __forceinline__ uint32_t smem_u32(const void* p) {
    uint32_t a;
    asm("{ .reg .u64 t; cvta.to.shared.u64 t, %1; cvt.u32.u64 %0, t; }" : "=r"(a) : "l"(p));
    return a;
}
#define SWZ128(o) ((o) ^ (((o) >> 3) & 0x70))

__device__ __forceinline__ void ldsm_x4(uint32_t* r, uint32_t addr) {
    asm volatile("ldmatrix.sync.aligned.m8n8.x4.shared.b16 {%0,%1,%2,%3}, [%4];"
                 : "=r"(r[0]), "=r"(r[1]), "=r"(r[2]), "=r"(r[3]) : "r"(addr));
}
__device__ __forceinline__ void mma16816h(float* d, const uint32_t* a, const uint32_t* b) {
    asm volatile(
        "mma.sync.aligned.m16n8k16.row.col.f32.f16.f16.f32 "
        "{%0,%1,%2,%3}, {%4,%5,%6,%7}, {%8,%9}, {%0,%1,%2,%3};"
        : "+f"(d[0]), "+f"(d[1]), "+f"(d[2]), "+f"(d[3])
        : "r"(a[0]), "r"(a[1]), "r"(a[2]), "r"(a[3]), "r"(b[0]), "r"(b[1]));
}
__device__ __forceinline__ void cp_async16(uint32_t daddr, const void* g, unsigned sz) {
    asm volatile("cp.async.cg.shared.global [%0], [%1], 16, %2;"
                 :: "r"(daddr), "l"(g), "r"(sz));
}
__device__ __forceinline__ void red_addf(float* p, float v) {
    asm volatile("red.global.add.f32 [%0], %1;" :: "l"(p), "f"(v) : "memory");
}
#define CP_COMMIT() asm volatile("cp.async.commit_group;" ::: "memory")
#define CP_WAIT(n)  asm volatile("cp.async.wait_group %0;" :: "n"(n) : "memory")

// =========================================================================
// prep kernels
// =========================================================================
__global__ void prep_misc_kernel(const float* __restrict__ input_,
                                 const float* __restrict__ b_ih0, const float* __restrict__ b_hh0,
                                 const float* __restrict__ b_ih1, const float* __restrict__ b_hh1) {
    int i = blockIdx.x * blockDim.x + threadIdx.x;
    if (i == 0) g_bar = 0u;
    if (i < GG) {
        g_bias0[i] = b_ih0[i] + b_hh0[i];
        g_bias1[i] = b_ih1[i] + b_hh1[i];
    }
    if (i < BB * DD) g_h1zf[i] = __float2half_rn(0.f);
    if (i < BB * DD / 4) {
        float4 v = *(const float4*)(input_ + i * 4);
        __half h[4] = {__float2half_rn(v.x), __float2half_rn(v.y),
                       __float2half_rn(v.z), __float2half_rn(v.w)};
        *(uint2*)(g_h0fA + i * 4) = *(uint2*)h;
    }
}

// fused: A1f = fp16(W_ih0)  AND  bias0f[g] = bias0[g] + W_ih0[g,:]·b_enc
__global__ void conv_a1_bias_kernel(const float* __restrict__ W_ih0,
                                    const float* __restrict__ b_enc) {
    __shared__ float red[256];
    int g = blockIdx.x;
    const float* src = W_ih0 + (size_t)g * VV;
    __half* dst = g_A1f + (size_t)g * VV;
    float s = 0.f;
    for (int v4 = threadIdx.x * 4; v4 < VV; v4 += 1024) {
        float4 v = *(const float4*)(src + v4);
        __half h[4] = {__float2half_rn(v.x), __float2half_rn(v.y),
                       __float2half_rn(v.z), __float2half_rn(v.w)};
        *(uint2*)(dst + v4) = *(uint2*)h;
        float4 b = *(const float4*)(b_enc + v4);
        s += v.x * b.x + v.y * b.y + v.z * b.z + v.w * b.w;
    }
    red[threadIdx.x] = s;
    __syncthreads();
    for (int o = 128; o > 0; o >>= 1) {
        if (threadIdx.x < o) red[threadIdx.x] += red[threadIdx.x + o];
        __syncthreads();
    }
    if (threadIdx.x == 0) g_bias0f[g] = g_bias0[g] + red[0];
}

// W_enc (10000,512) fp32 -> B1f (512,10000) fp16 transpose AND B2f fp16 copy
__global__ void conv_wenc_kernel(const float* __restrict__ src,
                                 __half* __restrict__ dstT, __half* __restrict__ dstN) {
    __shared__ float tile[32][33];
    int c0 = blockIdx.x * 32;
    int r0 = blockIdx.y * 32;
    int c = c0 + threadIdx.x;
    for (int i = threadIdx.y; i < 32; i += 8) {
        int r = r0 + i;
        if (r < VV) {
            float v = src[(size_t)r * DD + c];
            tile[i][threadIdx.x] = v;
            dstN[(size_t)r * DD + c] = __float2half_rn(v);   // non-transposed fp16
        }
    }
    __syncthreads();
    int r = r0 + threadIdx.x;
    if (r < VV) {
        for (int i = threadIdx.y; i < 32; i += 8)
            dstT[(size_t)(c0 + i) * VV + r] = __float2half_rn(tile[threadIdx.x][i]);
    }
}

// fused cell weights (fp16 single): out (2048,1024): n'=d*4+gate, src n=gate*512+d
__global__ void build_cell_w_kernel(const float* __restrict__ srcX, const float* __restrict__ srcH,
                                    __half* __restrict__ w) {
    int idx = blockIdx.x * 256 + threadIdx.x;
    int e = idx * 4;
    int np = e >> 10, k4 = e & 1023;
    int d = np >> 2, gate = np & 3;
    int n = gate * 512 + d;
    const float* s = (k4 < 512) ? (srcX + (size_t)n * 512 + k4)
                                : (srcH + (size_t)n * 512 + (k4 - 512));
    float4 v = *(const float4*)s;
    __half h[4] = {__float2half_rn(v.x), __float2half_rn(v.y),
                   __float2half_rn(v.z), __float2half_rn(v.w)};
    *(uint2*)(w + (size_t)np * 1024 + k4) = *(uint2*)h;
}

// =========================================================================
// GEMM1 (fp16 single, split-K=4): Mtmp(2048,512) += A(2048,10000)f16 @ B(512,10000)^T
// BM=256 (512 thr), BN=128, BK=64. grid (4, 8, 4) = 128 CTAs. KSPLIT=2560.
// =========================================================================
#define G1_BUF 49152
#define G1_SMEM (2 * G1_BUF)
#define KSPLIT 2560

__global__ __launch_bounds__(512) void gemm1_f16_kernel(
    const __half* __restrict__ A, const __half* __restrict__ B,
    float* __restrict__ C)
{
    extern __shared__ char smem[];
    const uint32_t sb = smem_u32(smem);
    const int tid = threadIdx.x, wid = tid >> 5, lane = tid & 31;
    const int wm = wid & 7, wn = wid >> 3;
    const int m0 = blockIdx.y * 256, n0 = blockIdx.x * 128;
    const int kb0 = blockIdx.z * KSPLIT;
    const int kend = min(kb0 + KSPLIT, VV);
    const int NT = (kend - kb0 + 63) / 64;

    float acc[2][8][4];
    #pragma unroll
    for (int mt = 0; mt < 2; mt++)
        #pragma unroll
        for (int nt = 0; nt < 8; nt++)
            #pragma unroll
            for (int j = 0; j < 4; j++) acc[mt][nt][j] = 0.f;

    auto load_chunk = [&](int kt, int buf) {
        const int kc = kb0 + kt * 64;
        const uint32_t bufbase = sb + buf * G1_BUF;
        #pragma unroll
        for (int it = 0; it < 4; it++) {
            int i = it * 512 + tid;
            int r = i >> 3, c16 = i & 7;
            int gk = kc + c16 * 8;
            bool inb = gk < kend;
            cp_async16(bufbase + SWZ128(r * 128 + c16 * 16),
                       A + (inb ? ((size_t)(m0 + r) * VV + gk) : 0), inb ? 16u : 0u);
        }
        #pragma unroll
        for (int it = 0; it < 2; it++) {
            int i = it * 512 + tid;
            int r = i >> 3, c16 = i & 7;
            int gk = kc + c16 * 8;
            bool inb = gk < kend;
            cp_async16(bufbase + 32768 + SWZ128(r * 128 + c16 * 16),
                       B + (inb ? ((size_t)(n0 + r) * VV + gk) : 0), inb ? 16u : 0u);
        }
        CP_COMMIT();
    };

    load_chunk(0, 0);
    const int g8 = lane >> 3, rg = lane & 7;

    for (int kt = 0; kt < NT; kt++) {
        const int buf = kt & 1;
        if (kt + 1 < NT) { load_chunk(kt + 1, buf ^ 1); CP_WAIT(1); }
        else             { CP_WAIT(0); }
        __syncthreads();

        const uint32_t bA = sb + buf * G1_BUF;
        const uint32_t bB = bA + 32768;

        #pragma unroll
        for (int kk = 0; kk < 4; kk++) {
            const int kb = kk * 32;
            uint32_t a4[2][4], b[8][2];
            #pragma unroll
            for (int mt = 0; mt < 2; mt++) {
                int row = wm * 32 + mt * 16 + (g8 & 1) * 8 + rg;
                ldsm_x4(a4[mt], bA + SWZ128(row * 128 + kb + (g8 >> 1) * 16));
            }
            #pragma unroll
            for (int p = 0; p < 4; p++) {
                int rowb = wn * 64 + p * 16 + (g8 >> 1) * 8 + rg;
                uint32_t t[4];
                ldsm_x4(t, bB + SWZ128(rowb * 128 + kb + (g8 & 1) * 16));
                b[2 * p][0] = t[0]; b[2 * p][1] = t[1];
                b[2 * p + 1][0] = t[2]; b[2 * p + 1][1] = t[3];
            }
            #pragma unroll
            for (int mt = 0; mt < 2; mt++)
                #pragma unroll
                for (int nt = 0; nt < 8; nt++)
                    mma16816h(acc[mt][nt], a4[mt], b[nt]);
        }
        __syncthreads();
    }

    #pragma unroll
    for (int mt = 0; mt < 2; mt++) {
        int row = m0 + wm * 32 + mt * 16 + (lane >> 2);
        #pragma unroll
        for (int nt = 0; nt < 8; nt++) {
            int col = n0 + wn * 64 + nt * 8 + (lane & 3) * 2;
            float* p0 = &C[(size_t)row * DD + col];
            float* p1 = &C[(size_t)(row + 8) * DD + col];
            red_addf(p0, acc[mt][nt][0]);
            red_addf(p0 + 1, acc[mt][nt][1]);
            red_addf(p1, acc[mt][nt][2]);
            red_addf(p1 + 1, acc[mt][nt][3]);
        }
    }
}

// =========================================================================
// GEMM2 (fp16 single-B): OUT(M,N) = A(M,K)f16 @ B(N,K)^T + bias.
// BM=256, BN=128, BK=64; 512 threads.
// =========================================================================
#define G2_BUF 49152
#define G2_SMEM (2 * G2_BUF)

__global__ __launch_bounds__(512) void gemm2_f16_kernel(
    const __half* __restrict__ A, const __half* __restrict__ B,
    float* __restrict__ C, const float* __restrict__ bias,
    int Mtot, int Ntot, int Ktot)
{
    extern __shared__ char smem[];
    const uint32_t sb = smem_u32(smem);
    const int tid = threadIdx.x, wid = tid >> 5, lane = tid & 31;
    const int wm = wid & 7, wn = wid >> 3;
    const int m0 = blockIdx.y * 256, n0 = blockIdx.x * 128;
    const int NT = (Ktot + 63) / 64;

    float acc[2][8][4];
    #pragma unroll
    for (int mt = 0; mt < 2; mt++)
        #pragma unroll
        for (int nt = 0; nt < 8; nt++)
            #pragma unroll
            for (int j = 0; j < 4; j++) acc[mt][nt][j] = 0.f;

    auto load_chunk = [&](int kt, int buf) {
        const int kc = kt * 64;
        const uint32_t bufbase = sb + buf * G2_BUF;
        #pragma unroll
        for (int it = 0; it < 4; it++) {
            int i = it * 512 + tid;
            int r = i >> 3, c16 = i & 7;
            cp_async16(bufbase + SWZ128(r * 128 + c16 * 16),
                       A + (size_t)(m0 + r) * Ktot + kc + c16 * 8, 16);
        }
        #pragma unroll
        for (int it = 0; it < 2; it++) {
            int i = it * 512 + tid;
            int r = i >> 3, c16 = i & 7;
            int gr = n0 + r;
            bool inb = gr < Ntot;
            cp_async16(bufbase + 32768 + SWZ128(r * 128 + c16 * 16),
                       B + (inb ? ((size_t)gr * Ktot + kc + c16 * 8) : 0), inb ? 16u : 0u);
        }
        CP_COMMIT();
    };

    load_chunk(0, 0);
    const int g8 = lane >> 3, rg = lane & 7;

    for (int kt = 0; kt < NT; kt++) {
        const int buf = kt & 1;
        if (kt + 1 < NT) { load_chunk(kt + 1, buf ^ 1); CP_WAIT(1); }
        else             { CP_WAIT(0); }
        __syncthreads();

        const uint32_t bA = sb + buf * G2_BUF;
        const uint32_t bB = bA + 32768;

        #pragma unroll
        for (int kk = 0; kk < 4; kk++) {
            const int kb = kk * 32;
            uint32_t a4[2][4], b[8][2];
            #pragma unroll
            for (int mt = 0; mt < 2; mt++) {
                int row = wm * 32 + mt * 16 + (g8 & 1) * 8 + rg;
                ldsm_x4(a4[mt], bA + SWZ128(row * 128 + kb + (g8 >> 1) * 16));
            }
            #pragma unroll
            for (int p = 0; p < 4; p++) {
                int rowb = wn * 64 + p * 16 + (g8 >> 1) * 8 + rg;
                uint32_t t[4];
                ldsm_x4(t, bB + SWZ128(rowb * 128 + kb + (g8 & 1) * 16));
                b[2 * p][0] = t[0]; b[2 * p][1] = t[1];
                b[2 * p + 1][0] = t[2]; b[2 * p + 1][1] = t[3];
            }
            #pragma unroll
            for (int mt = 0; mt < 2; mt++)
                #pragma unroll
                for (int nt = 0; nt < 8; nt++)
                    mma16816h(acc[mt][nt], a4[mt], b[nt]);
        }
        __syncthreads();
    }

    #pragma unroll
    for (int mt = 0; mt < 2; mt++) {
        int row = m0 + wm * 32 + mt * 16 + (lane >> 2);
        #pragma unroll
        for (int nt = 0; nt < 8; nt++) {
            int col = n0 + wn * 64 + nt * 8 + (lane & 3) * 2;
            if (col < Ntot) {
                float b0 = bias[col], b1 = bias[col + 1];
                float2 v0 = make_float2(acc[mt][nt][0] + b0, acc[mt][nt][1] + b1);
                float2 v1 = make_float2(acc[mt][nt][2] + b0, acc[mt][nt][3] + b1);
                *(float2*)&C[(size_t)row * Ntot + col] = v0;
                *(float2*)&C[(size_t)(row + 8) * Ntot + col] = v1;
            }
        }
    }
}

// =========================================================================
// persistent LSTM recurrence: 128 CTAs = 64 gate-slices x 2 batch-halves.
// CTA: 64 batch rows x 32 gate rows. 256 threads (4m x 2n warps).
// K-chunks of 128 (two 64-k SW128 sub-tiles, 16KB each, triple-buffered).
// h-part chunks (4..7) first, then x-part (0..3); grid-barrier WAIT deferred
// until just before the first x-chunk load. Arrive posted right after output.
// smem: W0 64K | W1 64K | A 3x16K | gates 64x33 f32
// =========================================================================
#define PSM_W0 0
#define PSM_W1 65536
#define PSM_A  131072
#define PSM_G  180224
#define GSTRIDE 33
#define PERS_SMEM (180224 + 64 * GSTRIDE * 4)

__global__ __launch_bounds__(256) void lstm_persistent_kernel(
    const __half* __restrict__ Wc0, const __half* __restrict__ Wc1,
    __half* __restrict__ h0fA, __half* __restrict__ h0fB,
    const __half* __restrict__ h1zf, __half* __restrict__ H1f,
    const float* __restrict__ bias0, const float* __restrict__ bias0f,
    const float* __restrict__ bias1)
{
    extern __shared__ char smem[];
    const uint32_t sb = smem_u32(smem);
    float* gates = (float*)(smem + PSM_G);
    const int tid = threadIdx.x, wid = tid >> 5, lane = tid & 31;
    const int gs = blockIdx.x >> 1;       // gate slice 0..63
    const int bh = blockIdx.x & 1;        // batch half
    const int n0 = gs * 32;
    const int b0 = bh * 64;
    const int wm = wid & 3, wn = wid >> 2;
    const int g8 = lane >> 3, rg = lane & 7;

    // persistent weight slices: per layer 16 x (32 rows x 128B 64-k chunks) = 64KB
    #pragma unroll
    for (int L = 0; L < 2; L++) {
        const __half* src = L ? Wc1 : Wc0;
        const uint32_t dstb = L ? PSM_W1 : PSM_W0;
        #pragma unroll
        for (int it = 0; it < 16; it++) {
            int i = it * 256 + tid;
            int ch = i >> 8, r = (i >> 3) & 31, c16 = i & 7;
            cp_async16(sb + dstb + ch * 4096 + SWZ128(r * 128 + c16 * 16),
                       src + (size_t)(n0 + r) * 1024 + ch * 64 + c16 * 8, 16);
        }
    }
    CP_COMMIT();

    float rb0[2][4], rb0f[2][4], rb1[2][4];
    #pragma unroll
    for (int it = 0; it < 2; it++) {
        int idx = it * 256 + tid;
        int dd = idx & 7;
        int d = gs * 8 + dd;
        #pragma unroll
        for (int g = 0; g < 4; g++) {
            rb0[it][g]  = bias0[g * 512 + d];
            rb0f[it][g] = bias0f[g * 512 + d];
            rb1[it][g]  = bias1[g * 512 + d];
        }
    }

    float c0r[2] = {0.f, 0.f}, c1r[2] = {0.f, 0.f};
    unsigned epoch = 0;
    int cur = 0;

    for (int t = 0; t < TT; t++) {
        #pragma unroll
        for (int layer = 0; layer < 2; layer++) {
            const __half *xf, *hf;
            int NJ;
            if (layer == 0) {
                NJ = (t == 0) ? 4 : 8;
                xf = (t == 0) ? (const __half*)0 : H1f + (size_t)(t - 1) * BB * DD;
                hf = cur ? h0fB : h0fA;
            } else {
                NJ = 8;
                xf = cur ? h0fA : h0fB;     // fresh h0 from layer 0 (this t)
                hf = (t == 0) ? h1zf : H1f + (size_t)(t - 1) * BB * DD;
            }
            const uint32_t wbase = sb + (layer ? PSM_W1 : PSM_W0);
            // 128-k chunks: h part = chunks 4..7, x part = 0..3; h first.
            auto chunk_of = [&](int j) { return (4 + j) & 7; };

            auto load_chunk = [&](int ch2, int buf) {
                const __half* src = (ch2 < 4) ? xf : hf;
                int koff = (ch2 & 3) * 128;
                const uint32_t base = sb + PSM_A + buf * 16384;
                #pragma unroll
                for (int it = 0; it < 4; it++) {
                    int i = it * 256 + tid;
                    int sub = i >> 9, r = (i >> 3) & 63, c16 = i & 7;
                    cp_async16(base + sub * 8192 + SWZ128(r * 128 + c16 * 16),
                               src + (size_t)(b0 + r) * 512 + koff + sub * 64 + c16 * 8, 16);
                }
                CP_COMMIT();
            };

            float acc[2][4];
            #pragma unroll
            for (int b = 0; b < 2; b++)
                #pragma unroll
                for (int j = 0; j < 4; j++) acc[b][j] = 0.f;

            load_chunk(chunk_of(0), 0);
            if (NJ > 1) load_chunk(chunk_of(1), 1);

            for (int j = 0; j < NJ; j++) {
                if (j + 1 < NJ) { CP_WAIT(1); }
                else            { CP_WAIT(0); }
                __syncthreads();
                if (j + 2 < NJ) {
                    // deferred grid-barrier wait before FIRST x-chunk load
                    if (chunk_of(j + 2) < 4 && chunk_of(j + 1) >= 4) {
                        if (tid == 0) {
                            unsigned target = epoch * NCTA;
                            volatile unsigned* p = &g_bar;
                            while (*p < target) { }
                            __threadfence();
                        }
                        __syncthreads();
                    }
                    load_chunk(chunk_of(j + 2), (j + 2) % 3);
                }

                const int ch2 = chunk_of(j);
                const uint32_t bA = sb + PSM_A + (j % 3) * 16384;

                #pragma unroll
                for (int kk = 0; kk < 8; kk++) {
                    const int sub = kk >> 2;
                    const int kb = (kk & 3) * 32;
                    const uint32_t bW = wbase + (ch2 * 2 + sub) * 4096;
                    uint32_t a4[4], tw[4];
                    int row = wm * 16 + (g8 & 1) * 8 + rg;
                    ldsm_x4(a4, bA + sub * 8192 + SWZ128(row * 128 + kb + (g8 >> 1) * 16));
                    int rowb = wn * 16 + (g8 >> 1) * 8 + rg;
                    ldsm_x4(tw, bW + SWZ128(rowb * 128 + kb + (g8 & 1) * 16));
                    uint32_t b0f[2] = {tw[0], tw[1]}, b1f[2] = {tw[2], tw[3]};
                    mma16816h(acc[0], a4, b0f);
                    mma16816h(acc[1], a4, b1f);
                }
            }
            __syncthreads();

            // stage gates (64 rows x 32 cols, stride 33)
            {
                int r0 = wm * 16 + (lane >> 2);
                int cb = wn * 16 + (lane & 3) * 2;
                #pragma unroll
                for (int b = 0; b < 2; b++) {
                    gates[r0 * GSTRIDE + cb + b * 8]           = acc[b][0];
                    gates[r0 * GSTRIDE + cb + b * 8 + 1]       = acc[b][1];
                    gates[(r0 + 8) * GSTRIDE + cb + b * 8]     = acc[b][2];
                    gates[(r0 + 8) * GSTRIDE + cb + b * 8 + 1] = acc[b][3];
                }
            }
            __syncthreads();

            __half* of = (layer == 0) ? (cur ? h0fA : h0fB) : (H1f + (size_t)t * BB * DD);
            #pragma unroll
            for (int it = 0; it < 2; it++) {
                int idx = it * 256 + tid;
                int row = idx >> 3, dd = idx & 7;
                int d = gs * 8 + dd;
                const float* rb = (layer == 0) ? ((t == 0) ? rb0[it] : rb0f[it]) : rb1[it];
                float gi = gates[row * GSTRIDE + dd * 4 + 0] + rb[0];
                float gf = gates[row * GSTRIDE + dd * 4 + 1] + rb[1];
                float gg = gates[row * GSTRIDE + dd * 4 + 2] + rb[2];
                float go = gates[row * GSTRIDE + dd * 4 + 3] + rb[3];
                float i_ = 1.f / (1.f + expf(-gi));
                float f_ = 1.f / (1.f + expf(-gf));
                float g_ = tanhf(gg);
                float o_ = 1.f / (1.f + expf(-go));
                float* cr = (layer == 0) ? &c0r[it] : &c1r[it];
                float cn = f_ * (*cr) + i_ * g_;
                *cr = cn;
                of[(size_t)(b0 + row) * 512 + d] = __float2half_rn(o_ * tanhf(cn));
            }

            // arrive (no wait here — wait is deferred into next phase)
            __threadfence();
            __syncthreads();
            if (tid == 0) atomicAdd(&g_bar, 1u);
            epoch++;
        }
        cur ^= 1;
    }
}

// =========================================================================
// host
// =========================================================================
extern "C" void kernel_launch(void* const* d_in, const int* in_sizes, int n_in,
                              void* d_out, int out_size) {
    const float* input_ = (const float*)d_in[0];
    const float* W_ih0  = (const float*)d_in[1];
    const float* W_hh0  = (const float*)d_in[2];
    const float* b_ih0  = (const float*)d_in[3];
    const float* b_hh0  = (const float*)d_in[4];
    const float* W_ih1  = (const float*)d_in[5];
    const float* W_hh1  = (const float*)d_in[6];
    const float* b_ih1  = (const float*)d_in[7];
    const float* b_hh1  = (const float*)d_in[8];
    const float* W_enc  = (const float*)d_in[9];
    const float* b_enc  = (const float*)d_in[10];
    float* out = (float*)d_out;

    float *p_Mtmp, *p_bias0, *p_bias0f, *p_bias1;
    __half *p_A1f, *p_B1f, *p_B2f;
    __half *p_H1f, *p_h0fA, *p_h0fB, *p_h1zf, *p_Wc0, *p_Wc1;
    cudaGetSymbolAddress((void**)&p_Mtmp,   g_Mtmp);
    cudaGetSymbolAddress((void**)&p_bias0,  g_bias0);
    cudaGetSymbolAddress((void**)&p_bias0f, g_bias0f);
    cudaGetSymbolAddress((void**)&p_bias1,  g_bias1);
    cudaGetSymbolAddress((void**)&p_A1f,    g_A1f);
    cudaGetSymbolAddress((void**)&p_B1f,    g_B1f);
    cudaGetSymbolAddress((void**)&p_B2f,    g_B2f);
    cudaGetSymbolAddress((void**)&p_H1f,    g_H1f);
    cudaGetSymbolAddress((void**)&p_h0fA,   g_h0fA);
    cudaGetSymbolAddress((void**)&p_h0fB,   g_h0fB);
    cudaGetSymbolAddress((void**)&p_h1zf,   g_h1zf);
    cudaGetSymbolAddress((void**)&p_Wc0,    g_Wc0);
    cudaGetSymbolAddress((void**)&p_Wc1,    g_Wc1);

    cudaFuncSetAttribute((const void*)gemm1_f16_kernel,
                         cudaFuncAttributeMaxDynamicSharedMemorySize, G1_SMEM);
    cudaFuncSetAttribute((const void*)gemm2_f16_kernel,
                         cudaFuncAttributeMaxDynamicSharedMemorySize, G2_SMEM);
    cudaFuncSetAttribute((const void*)lstm_persistent_kernel,
                         cudaFuncAttributeMaxDynamicSharedMemorySize, PERS_SMEM);

    // ---- prep ----
    prep_misc_kernel<<<(BB * DD + 255) / 256, 256>>>(input_, b_ih0, b_hh0, b_ih1, b_hh1);
    cudaMemsetAsync(p_Mtmp, 0, (size_t)GG * DD * sizeof(float));
    conv_a1_bias_kernel<<<GG, 256>>>(W_ih0, b_enc);   // A1f + bias0f in one pass

    dim3 tb(32, 8);
    conv_wenc_kernel<<<dim3(DD / 32, (VV + 31) / 32), tb>>>(W_enc, p_B1f, p_B2f);

    // GEMM1: Mtmp += W_ih0 @ W_enc^T  [fp16 single, BM=256, split-K=4, 128 CTAs]
    gemm1_f16_kernel<<<dim3(DD / 128, GG / 256, 4), 512, G1_SMEM>>>(
        p_A1f, p_B1f, p_Mtmp);

    // fused, gate-interleaved fp16 cell weights (single term)
    build_cell_w_kernel<<<2048, 256>>>(p_Mtmp, W_hh0, p_Wc0);
    build_cell_w_kernel<<<2048, 256>>>(W_ih1, W_hh1, p_Wc1);

    // ---- recurrence: one persistent launch, 128 CTAs (batch-split) ----
    lstm_persistent_kernel<<<NCTA, 256, PERS_SMEM>>>(
        p_Wc0, p_Wc1, p_h0fA, p_h0fB, p_h1zf, p_H1f,
        p_bias0, p_bias0f, p_bias1);

    // GEMM2: OUT(2560,10000) = H1f @ B2f^T + b_enc  [fp16 single-B]
    gemm2_f16_kernel<<<dim3((VV + 127) / 128, (TT * BB) / 256), 512, G2_SMEM>>>(
        p_H1f, p_B2f, out, b_enc, TT * BB, VV, DD);
}